// round 1
// baseline (speedup 1.0000x reference)
#include <cuda_runtime.h>
#include <cmath>

// Problem constants
#define BT    8192      // B*T
#define DDIM  4096
#define NH    512       // G*C*K hidden cols
#define NDD   128       // 4*M dd cols
#define CNUM  4
#define KDIM  128
#define MDIM  32

// Output layout inside d_out (f32):
//   w1n: [8192, 4, 2, 32]  at offset 0            (2,097,152)
//   w2 : [8192, 4, 2, 32]  at offset 2,097,152
//   dd : [8192, 128]       at offset 4,194,304
#define W2_BASE  (BT * CNUM * 2 * MDIM)
#define DD_BASE  (2 * W2_BASE)

// Scratch for gelu(X @ dw1): 8192 x 512 f32 = 16 MB
__device__ float g_hidden[(size_t)BT * NH];

__device__ __forceinline__ float gelu_exact(float x) {
    return 0.5f * x * (1.0f + erff(x * 0.70710678118654752f));
}

// ---------------------------------------------------------------------------
// Kernel 1: Y[8192, 640] = X[8192,4096] @ [dw1 | dd_p]
//   cols <  512: gelu -> g_hidden
//   cols >= 512: tanh -> dd output
// Tile: BM=128, BN=64, BK=16; 256 threads; 8x4 per-thread
// ---------------------------------------------------------------------------
#define BM1 128
#define BN1 64
#define BK1 16

__global__ __launch_bounds__(256) void gemm1_fused(
    const float* __restrict__ X,    // [8192,4096]
    const float* __restrict__ W1,   // dw1 [4096,512]
    const float* __restrict__ Wd,   // dd_p [4096,128]
    float* __restrict__ dd_out)     // d_out + DD_BASE
{
    __shared__ float As[BK1][BM1];
    __shared__ float Bs[BK1][BN1];

    const int tx    = threadIdx.x;
    const int mbase = blockIdx.y * BM1;
    const int nbase = blockIdx.x * BN1;
    const int tRow  = tx >> 4;   // 0..15
    const int tCol  = tx & 15;   // 0..15

    const bool isDD = (nbase >= NH);
    const float* Wsrc = isDD ? Wd : W1;
    const int ldw   = isDD ? NDD : NH;
    const int ncol0 = isDD ? (nbase - NH) : nbase;

    float acc[8][4];
    #pragma unroll
    for (int i = 0; i < 8; ++i)
        #pragma unroll
        for (int j = 0; j < 4; ++j) acc[i][j] = 0.0f;

    for (int k0 = 0; k0 < DDIM; k0 += BK1) {
        // Load A tile (128 rows x 16 k), transposed into As[k][m]
        #pragma unroll
        for (int s = tx; s < 512; s += 256) {
            int row = s >> 2;
            int kq  = (s & 3) << 2;
            float4 v = *reinterpret_cast<const float4*>(
                &X[(size_t)(mbase + row) * DDIM + k0 + kq]);
            As[kq + 0][row] = v.x;
            As[kq + 1][row] = v.y;
            As[kq + 2][row] = v.z;
            As[kq + 3][row] = v.w;
        }
        // Load B tile (16 k x 64 n)
        {
            int krow = tx >> 4;
            int n4   = (tx & 15) << 2;
            float4 v = *reinterpret_cast<const float4*>(
                &Wsrc[(size_t)(k0 + krow) * ldw + ncol0 + n4]);
            *reinterpret_cast<float4*>(&Bs[krow][n4]) = v;
        }
        __syncthreads();

        #pragma unroll
        for (int k = 0; k < BK1; ++k) {
            float a[8], b[4];
            float4 a0 = *reinterpret_cast<const float4*>(&As[k][tRow * 8]);
            float4 a1 = *reinterpret_cast<const float4*>(&As[k][tRow * 8 + 4]);
            a[0]=a0.x; a[1]=a0.y; a[2]=a0.z; a[3]=a0.w;
            a[4]=a1.x; a[5]=a1.y; a[6]=a1.z; a[7]=a1.w;
            float4 b0 = *reinterpret_cast<const float4*>(&Bs[k][tCol * 4]);
            b[0]=b0.x; b[1]=b0.y; b[2]=b0.z; b[3]=b0.w;
            #pragma unroll
            for (int i = 0; i < 8; ++i)
                #pragma unroll
                for (int j = 0; j < 4; ++j)
                    acc[i][j] = fmaf(a[i], b[j], acc[i][j]);
        }
        __syncthreads();
    }

    // Epilogue
    #pragma unroll
    for (int i = 0; i < 8; ++i) {
        int r = mbase + tRow * 8 + i;
        if (!isDD) {
            float4 o;
            o.x = gelu_exact(acc[i][0]);
            o.y = gelu_exact(acc[i][1]);
            o.z = gelu_exact(acc[i][2]);
            o.w = gelu_exact(acc[i][3]);
            *reinterpret_cast<float4*>(
                &g_hidden[(size_t)r * NH + nbase + tCol * 4]) = o;
        } else {
            float4 o;
            o.x = tanhf(acc[i][0]);
            o.y = tanhf(acc[i][1]);
            o.z = tanhf(acc[i][2]);
            o.w = tanhf(acc[i][3]);
            *reinterpret_cast<float4*>(
                &dd_out[(size_t)r * NDD + ncol0 + tCol * 4]) = o;
        }
    }
}

// ---------------------------------------------------------------------------
// Kernel 2: per (row-tile, c): dw[128,128] = hidden[:,c*128:(c+1)*128] @ qkw[c]
// Epilogue: cols j = ii*32 + m; ii<2 -> RMS-norm over m (32) -> w1n; ii>=2 -> w2
// Tile: BM=128, N=128 (full), BK=16; 256 threads; 8x8 per-thread
// RMS reduction: each (row, ii) group of 32 cols is held by 4 adjacent lanes
// (8 cols each) -> two shfl_xor steps.
// ---------------------------------------------------------------------------
#define BK2 16

__global__ __launch_bounds__(256) void gemm2_rms(
    const float* __restrict__ qkw,  // [4,128,128] (c, k, j)
    float* __restrict__ w1n_out,    // d_out
    float* __restrict__ w2_out)     // d_out + W2_BASE
{
    const int c     = blockIdx.x;        // 0..3
    const int mbase = blockIdx.y * 128;

    __shared__ float As[BK2][128];
    __shared__ float Ws[BK2][128];

    const int tx   = threadIdx.x;
    const int tRow = tx >> 4;  // 0..15
    const int tCol = tx & 15;  // 0..15

    float acc[8][8];
    #pragma unroll
    for (int i = 0; i < 8; ++i)
        #pragma unroll
        for (int j = 0; j < 8; ++j) acc[i][j] = 0.0f;

    for (int k0 = 0; k0 < KDIM; k0 += BK2) {
        // A: hidden[mbase+row][c*128 + k0 + kq], transposed
        #pragma unroll
        for (int s = tx; s < 512; s += 256) {
            int row = s >> 2;
            int kq  = (s & 3) << 2;
            float4 v = *reinterpret_cast<const float4*>(
                &g_hidden[(size_t)(mbase + row) * NH + c * KDIM + k0 + kq]);
            As[kq + 0][row] = v.x;
            As[kq + 1][row] = v.y;
            As[kq + 2][row] = v.z;
            As[kq + 3][row] = v.w;
        }
        // W: qkw[c][k0+krow][j]  (16 rows x 128 cols)
        #pragma unroll
        for (int s = tx; s < 512; s += 256) {
            int krow = s >> 5;           // 0..15
            int j4   = (s & 31) << 2;    // 0..124
            float4 v = *reinterpret_cast<const float4*>(
                &qkw[((size_t)c * KDIM + k0 + krow) * 128 + j4]);
            *reinterpret_cast<float4*>(&Ws[krow][j4]) = v;
        }
        __syncthreads();

        #pragma unroll
        for (int k = 0; k < BK2; ++k) {
            float a[8], b[8];
            float4 a0 = *reinterpret_cast<const float4*>(&As[k][tRow * 8]);
            float4 a1 = *reinterpret_cast<const float4*>(&As[k][tRow * 8 + 4]);
            a[0]=a0.x; a[1]=a0.y; a[2]=a0.z; a[3]=a0.w;
            a[4]=a1.x; a[5]=a1.y; a[6]=a1.z; a[7]=a1.w;
            float4 b0 = *reinterpret_cast<const float4*>(&Ws[k][tCol * 8]);
            float4 b1 = *reinterpret_cast<const float4*>(&Ws[k][tCol * 8 + 4]);
            b[0]=b0.x; b[1]=b0.y; b[2]=b0.z; b[3]=b0.w;
            b[4]=b1.x; b[5]=b1.y; b[6]=b1.z; b[7]=b1.w;
            #pragma unroll
            for (int i = 0; i < 8; ++i)
                #pragma unroll
                for (int j = 0; j < 8; ++j)
                    acc[i][j] = fmaf(a[i], b[j], acc[i][j]);
        }
        __syncthreads();
    }

    // Epilogue: thread owns cols [tCol*8, tCol*8+8) => ii = tCol/4,
    // local m offset = (tCol%4)*8
    const int ii   = tCol >> 2;        // 0..3
    const int mloc = (tCol & 3) * 8;   // 0,8,16,24

    #pragma unroll
    for (int i = 0; i < 8; ++i) {
        int r = mbase + tRow * 8 + i;
        float ss = 0.0f;
        #pragma unroll
        for (int j = 0; j < 8; ++j) ss = fmaf(acc[i][j], acc[i][j], ss);
        ss += __shfl_xor_sync(0xffffffffu, ss, 1);
        ss += __shfl_xor_sync(0xffffffffu, ss, 2);

        if (ii < 2) {
            float scale = rsqrtf(ss * (1.0f / 32.0f) + 1e-6f);
            float4 o0, o1;
            o0.x = acc[i][0] * scale; o0.y = acc[i][1] * scale;
            o0.z = acc[i][2] * scale; o0.w = acc[i][3] * scale;
            o1.x = acc[i][4] * scale; o1.y = acc[i][5] * scale;
            o1.z = acc[i][6] * scale; o1.w = acc[i][7] * scale;
            size_t base = (size_t)r * 256 + (size_t)c * 64 + ii * 32 + mloc;
            *reinterpret_cast<float4*>(&w1n_out[base])     = o0;
            *reinterpret_cast<float4*>(&w1n_out[base + 4]) = o1;
        } else {
            float4 o0, o1;
            o0.x = acc[i][0]; o0.y = acc[i][1];
            o0.z = acc[i][2]; o0.w = acc[i][3];
            o1.x = acc[i][4]; o1.y = acc[i][5];
            o1.z = acc[i][6]; o1.w = acc[i][7];
            size_t base = (size_t)r * 256 + (size_t)c * 64 + (ii - 2) * 32 + mloc;
            *reinterpret_cast<float4*>(&w2_out[base])     = o0;
            *reinterpret_cast<float4*>(&w2_out[base + 4]) = o1;
        }
    }
}

extern "C" void kernel_launch(void* const* d_in, const int* in_sizes, int n_in,
                              void* d_out, int out_size) {
    const float* query = (const float*)d_in[0];
    // d_in[1] = key_vec (unused by the reference)
    const float* dw1   = (const float*)d_in[2];
    const float* qkw   = (const float*)d_in[3];
    const float* dd_p  = (const float*)d_in[4];

    float* out  = (float*)d_out;
    float* w1n  = out;
    float* w2   = out + W2_BASE;
    float* dd   = out + DD_BASE;

    // Kernel 1: N = 640 combined (512 hidden + 128 dd), tiles of 64
    dim3 grid1((NH + NDD) / BN1, BT / BM1);   // (10, 64)
    gemm1_fused<<<grid1, 256>>>(query, dw1, dd_p, dd);

    // Kernel 2: (c, row-tile)
    dim3 grid2(CNUM, BT / 128);               // (4, 64)
    gemm2_rms<<<grid2, 256>>>(qkw, w1n, w2);
}

// round 3
// speedup vs baseline: 1.9942x; 1.9942x over previous
#include <cuda_runtime.h>
#include <cuda_bf16.h>
#include <cmath>
#include <cstdint>

// ---------------- problem constants ----------------
#define BT    8192
#define DDIM  4096
#define NH    512       // hidden cols (G*C*K)
#define NDD   128       // dd cols (4M)
#define NTOT  640       // NH + NDD
#define CNUM  4
#define KDIM  128

#define W2_BASE  (BT * CNUM * 2 * 32)   // 2,097,152
#define DD_BASE  (2 * W2_BASE)

// ---------------- device scratch ----------------
__device__ __nv_bfloat16 g_Xhi[(size_t)BT * DDIM];
__device__ __nv_bfloat16 g_Xlo[(size_t)BT * DDIM];
__device__ __nv_bfloat16 g_Whi[(size_t)NTOT * DDIM];   // [n][k] (K-major)
__device__ __nv_bfloat16 g_Wlo[(size_t)NTOT * DDIM];
// hidden stored TRANSPOSED: g_hiddenT[col][row]
__device__ float g_hiddenT[(size_t)NH * BT];

__device__ __forceinline__ float gelu_exact(float x) {
    return 0.5f * x * (1.0f + erff(x * 0.70710678118654752f));
}

#define CPA16(dst, src) \
    asm volatile("cp.async.cg.shared.global [%0], [%1], 16;" :: "r"(dst), "l"(src) : "memory")
#define CPA_COMMIT() asm volatile("cp.async.commit_group;" ::: "memory")
#define CPA_WAIT2()  asm volatile("cp.async.wait_group 2;" ::: "memory")

__device__ __forceinline__ uint32_t smem_u32(const void* p) {
    uint32_t a;
    asm("{ .reg .u64 t; cvta.to.shared.u64 t, %1; cvt.u32.u64 %0, t; }" : "=r"(a) : "l"(p));
    return a;
}

__device__ __forceinline__ void mma16816(float* d, const uint32_t* a, const uint32_t* b) {
    asm volatile(
        "mma.sync.aligned.m16n8k16.row.col.f32.bf16.bf16.f32 "
        "{%0,%1,%2,%3}, {%4,%5,%6,%7}, {%8,%9}, {%0,%1,%2,%3};"
        : "+f"(d[0]), "+f"(d[1]), "+f"(d[2]), "+f"(d[3])
        : "r"(a[0]), "r"(a[1]), "r"(a[2]), "r"(a[3]), "r"(b[0]), "r"(b[1]));
}

// ---------------------------------------------------------------------------
// conv_x: X f32 -> Xhi/Xlo bf16
// ---------------------------------------------------------------------------
__global__ __launch_bounds__(256) void conv_x(const float4* __restrict__ X) {
    size_t n = (size_t)BT * DDIM / 4;
    uint2* XH = reinterpret_cast<uint2*>(g_Xhi);
    uint2* XL = reinterpret_cast<uint2*>(g_Xlo);
    for (size_t i = (size_t)blockIdx.x * blockDim.x + threadIdx.x; i < n;
         i += (size_t)gridDim.x * blockDim.x) {
        float4 v = X[i];
        float f[4] = {v.x, v.y, v.z, v.w};
        uint32_t hp[2] = {0, 0}, lp[2] = {0, 0};
        #pragma unroll
        for (int j = 0; j < 4; ++j) {
            __nv_bfloat16 h = __float2bfloat16_rn(f[j]);
            float lo = f[j] - __bfloat162float(h);
            __nv_bfloat16 l = __float2bfloat16_rn(lo);
            hp[j >> 1] |= (uint32_t)__bfloat16_as_ushort(h) << ((j & 1) * 16);
            lp[j >> 1] |= (uint32_t)__bfloat16_as_ushort(l) << ((j & 1) * 16);
        }
        XH[i] = make_uint2(hp[0], hp[1]);
        XL[i] = make_uint2(lp[0], lp[1]);
    }
}

// ---------------------------------------------------------------------------
// conv_w: transpose+split [dw1 | dd_p] -> Whi/Wlo [640][4096] (K-major)
// ---------------------------------------------------------------------------
__global__ __launch_bounds__(256) void conv_w(const float* __restrict__ dw1,
                                              const float* __restrict__ ddp) {
    __shared__ float t[32][33];
    int n0 = blockIdx.x * 32, k0 = blockIdx.y * 32;
    int tx = threadIdx.x, ty = threadIdx.y;  // 32 x 8
    const float* src = (n0 < NH) ? dw1 : ddp;
    int ld   = (n0 < NH) ? NH : NDD;
    int ncol = (n0 < NH) ? (n0 + tx) : (n0 - NH + tx);
    #pragma unroll
    for (int j = 0; j < 4; ++j)
        t[ty + 8 * j][tx] = src[(size_t)(k0 + ty + 8 * j) * ld + ncol];
    __syncthreads();
    #pragma unroll
    for (int j = 0; j < 4; ++j) {
        int n = n0 + ty + 8 * j, k = k0 + tx;
        float v = t[tx][ty + 8 * j];
        __nv_bfloat16 h = __float2bfloat16_rn(v);
        g_Whi[(size_t)n * DDIM + k] = h;
        g_Wlo[(size_t)n * DDIM + k] = __float2bfloat16_rn(v - __bfloat162float(h));
    }
}

// ---------------------------------------------------------------------------
// gemm1_mma: [8192,4096] x [4096,640] via mma.sync bf16 (3-term fp32 split)
// CTA 128x128, BK=32, 3-stage cp.async. 256 threads, warp grid 2(M)x4(N),
// warp tile 64x32 (4x4 m16n8k16 tiles).
// Smem tile: [128 rows][40 bf16] (pad 8) = 10240 B; 4 tiles/stage = 40960 B.
// ---------------------------------------------------------------------------
#define LDB    40            // padded row length in bf16
#define TILE_B (128 * LDB * 2)   // 10240
#define STAGE_B (4 * TILE_B)     // 40960
#define STAGES 3
#define GEMM1_SMEM (STAGES * STAGE_B)   // 122880

__global__ __launch_bounds__(256, 1) void gemm1_mma(float* __restrict__ dd_out) {
    extern __shared__ char smem[];
    uint32_t sb = smem_u32(smem);

    const int tid  = threadIdx.x;
    const int wid  = tid >> 5;
    const int lane = tid & 31;
    const int g    = lane >> 2;     // group id 0..7
    const int tg   = lane & 3;      // thread-in-group

    const int ntile = blockIdx.x;   // 0..4
    const int mbase = blockIdx.y << 7;
    const int m0w   = (wid & 1) * 64;   // warp M offset in CTA
    const int n0w   = (wid >> 1) * 32;  // warp N offset in CTA

    const __nv_bfloat16* aHi = g_Xhi + (size_t)mbase * DDIM;
    const __nv_bfloat16* aLo = g_Xlo + (size_t)mbase * DDIM;
    const __nv_bfloat16* bHi = g_Whi + (size_t)(ntile * 128) * DDIM;
    const __nv_bfloat16* bLo = g_Wlo + (size_t)(ntile * 128) * DDIM;

    // load geometry: 2 chunks of 16B per tile per thread
    // chunk c: row = c>>2, c16 = c&3 (16B within 32 bf16 row)
    int c0 = tid, c1 = tid + 256;
    int r0 = c0 >> 2, q0 = c0 & 3;
    int r1 = c1 >> 2, q1 = c1 & 3;
    uint32_t d0 = (uint32_t)(r0 * LDB * 2 + q0 * 16);
    uint32_t d1 = (uint32_t)(r1 * LDB * 2 + q1 * 16);
    uint32_t s0 = (uint32_t)(r0 * DDIM + q0 * 8);
    uint32_t s1 = (uint32_t)(r1 * DDIM + q1 * 8);

    auto load_stage = [&](int st, int k0) {
        uint32_t tb = sb + st * STAGE_B;
        CPA16(tb + d0,              aHi + s0 + k0);
        CPA16(tb + d1,              aLo + s1 + k0 - 0 + (s1 - s1)); // placeholder avoided below
    };
    (void)load_stage; // not used; explicit below for clarity

    const int NKT = DDIM / 32;   // 128

    float acc[4][4][4];
    #pragma unroll
    for (int mi = 0; mi < 4; ++mi)
        #pragma unroll
        for (int ni = 0; ni < 4; ++ni)
            #pragma unroll
            for (int r = 0; r < 4; ++r) acc[mi][ni][r] = 0.0f;

    // prologue: fill 3 stages
    #pragma unroll
    for (int st = 0; st < STAGES; ++st) {
        uint32_t tb = sb + st * STAGE_B;
        int k0 = st * 32;
        CPA16(tb + d0,              aHi + s0 + k0);
        CPA16(tb + d1,              aHi + s1 + k0);
        CPA16(tb + TILE_B + d0,     aLo + s0 + k0);
        CPA16(tb + TILE_B + d1,     aLo + s1 + k0);
        CPA16(tb + 2 * TILE_B + d0, bHi + s0 + k0);
        CPA16(tb + 2 * TILE_B + d1, bHi + s1 + k0);
        CPA16(tb + 3 * TILE_B + d0, bLo + s0 + k0);
        CPA16(tb + 3 * TILE_B + d1, bLo + s1 + k0);
        CPA_COMMIT();
    }

    const __nv_bfloat16* smb = reinterpret_cast<const __nv_bfloat16*>(smem);

    for (int it = 0; it < NKT; ++it) {
        int st = it % STAGES;
        CPA_WAIT2();
        __syncthreads();

        const __nv_bfloat16* Ahi = smb + (size_t)st * STAGE_B / 2;
        const __nv_bfloat16* Alo = Ahi + TILE_B / 2;
        const __nv_bfloat16* Bhi = Alo + TILE_B / 2;
        const __nv_bfloat16* Blo = Bhi + TILE_B / 2;

        #pragma unroll
        for (int ks = 0; ks < 32; ks += 16) {
            // B fragments: 4 n-tiles, hi & lo
            uint32_t bh[4][2], bl[4][2];
            #pragma unroll
            for (int ni = 0; ni < 4; ++ni) {
                int n = n0w + ni * 8 + g;
                const uint32_t* ph = reinterpret_cast<const uint32_t*>(&Bhi[n * LDB + ks + tg * 2]);
                const uint32_t* pl = reinterpret_cast<const uint32_t*>(&Blo[n * LDB + ks + tg * 2]);
                bh[ni][0] = ph[0]; bh[ni][1] = ph[4];
                bl[ni][0] = pl[0]; bl[ni][1] = pl[4];
            }
            #pragma unroll
            for (int mi = 0; mi < 4; ++mi) {
                int m = m0w + mi * 16 + g;
                uint32_t ah[4], al[4];
                const uint32_t* ph0 = reinterpret_cast<const uint32_t*>(&Ahi[m * LDB + ks + tg * 2]);
                const uint32_t* ph1 = reinterpret_cast<const uint32_t*>(&Ahi[(m + 8) * LDB + ks + tg * 2]);
                const uint32_t* pl0 = reinterpret_cast<const uint32_t*>(&Alo[m * LDB + ks + tg * 2]);
                const uint32_t* pl1 = reinterpret_cast<const uint32_t*>(&Alo[(m + 8) * LDB + ks + tg * 2]);
                ah[0] = ph0[0]; ah[1] = ph1[0]; ah[2] = ph0[4]; ah[3] = ph1[4];
                al[0] = pl0[0]; al[1] = pl1[0]; al[2] = pl0[4]; al[3] = pl1[4];
                #pragma unroll
                for (int ni = 0; ni < 4; ++ni) {
                    mma16816(acc[mi][ni], ah, bh[ni]);
                    mma16816(acc[mi][ni], ah, bl[ni]);
                    mma16816(acc[mi][ni], al, bh[ni]);
                }
            }
        }

        __syncthreads();
        if (it + STAGES < NKT) {
            uint32_t tb = sb + st * STAGE_B;
            int k0 = (it + STAGES) * 32;
            CPA16(tb + d0,              aHi + s0 + k0);
            CPA16(tb + d1,              aHi + s1 + k0);
            CPA16(tb + TILE_B + d0,     aLo + s0 + k0);
            CPA16(tb + TILE_B + d1,     aLo + s1 + k0);
            CPA16(tb + 2 * TILE_B + d0, bHi + s0 + k0);
            CPA16(tb + 2 * TILE_B + d1, bHi + s1 + k0);
            CPA16(tb + 3 * TILE_B + d0, bLo + s0 + k0);
            CPA16(tb + 3 * TILE_B + d1, bLo + s1 + k0);
        }
        CPA_COMMIT();
    }

    // ---------------- epilogue ----------------
    if (ntile < 4) {
        // gelu -> smem transpose buffer [col][row] pad -> coalesced hiddenT stores
        __syncthreads();
        float* smT = reinterpret_cast<float*>(smem);   // [128 cols][136 rows]
        #pragma unroll
        for (int mi = 0; mi < 4; ++mi) {
            #pragma unroll
            for (int ni = 0; ni < 4; ++ni) {
                int row = m0w + mi * 16 + g;
                int col = n0w + ni * 8 + tg * 2;
                smT[(size_t)col * 136 + row]           = gelu_exact(acc[mi][ni][0]);
                smT[(size_t)(col + 1) * 136 + row]     = gelu_exact(acc[mi][ni][1]);
                smT[(size_t)col * 136 + row + 8]       = gelu_exact(acc[mi][ni][2]);
                smT[(size_t)(col + 1) * 136 + row + 8] = gelu_exact(acc[mi][ni][3]);
            }
        }
        __syncthreads();
        // 128 cols x 128 rows -> float4 chunks; 4096 chunks / 256 threads = 16
        #pragma unroll
        for (int i = 0; i < 16; ++i) {
            int c   = tid + i * 256;
            int col = c >> 5;
            int rr  = (c & 31) << 2;
            float4 o;
            o.x = smT[(size_t)col * 136 + rr + 0];
            o.y = smT[(size_t)col * 136 + rr + 1];
            o.z = smT[(size_t)col * 136 + rr + 2];
            o.w = smT[(size_t)col * 136 + rr + 3];
            *reinterpret_cast<float4*>(
                &g_hiddenT[((size_t)(ntile * 128 + col) << 13) + mbase + rr]) = o;
        }
    } else {
        // dd: tanh, direct row-major float2 stores
        #pragma unroll
        for (int mi = 0; mi < 4; ++mi) {
            #pragma unroll
            for (int ni = 0; ni < 4; ++ni) {
                int row = mbase + m0w + mi * 16 + g;
                int col = n0w + ni * 8 + tg * 2;
                float2 o0 = make_float2(tanhf(acc[mi][ni][0]), tanhf(acc[mi][ni][1]));
                float2 o1 = make_float2(tanhf(acc[mi][ni][2]), tanhf(acc[mi][ni][3]));
                *reinterpret_cast<float2*>(&dd_out[(size_t)row * NDD + col])       = o0;
                *reinterpret_cast<float2*>(&dd_out[(size_t)(row + 8) * NDD + col]) = o1;
            }
        }
    }
}

// ---------------------------------------------------------------------------
// gemm2: per (row-tile, c): dw[128,128] = hiddenT chunk @ qkw[c]; RMS epilogue
// ---------------------------------------------------------------------------
#define BK2 16

__global__ __launch_bounds__(256) void gemm2_rms(
    const float* __restrict__ qkw,
    float* __restrict__ w1n_out,
    float* __restrict__ w2_out) {
    const int c     = blockIdx.x;
    const int mbase = blockIdx.y * 128;

    __shared__ float As[BK2][128];
    __shared__ float Ws[BK2][128];

    const int tx = threadIdx.x;
    const int tRow = tx >> 4, tCol = tx & 15;

    float acc[8][8];
    #pragma unroll
    for (int i = 0; i < 8; ++i)
        #pragma unroll
        for (int j = 0; j < 8; ++j) acc[i][j] = 0.0f;

    for (int k0 = 0; k0 < KDIM; k0 += BK2) {
        #pragma unroll
        for (int s = tx; s < 512; s += 256) {
            int k  = s >> 5;
            int r4 = (s & 31) << 2;
            float4 v = *reinterpret_cast<const float4*>(
                &g_hiddenT[((size_t)(c * KDIM + k0 + k) << 13) + mbase + r4]);
            *reinterpret_cast<float4*>(&As[k][r4]) = v;
        }
        #pragma unroll
        for (int s = tx; s < 512; s += 256) {
            int krow = s >> 5;
            int j4   = (s & 31) << 2;
            float4 v = *reinterpret_cast<const float4*>(
                &qkw[((size_t)c * KDIM + k0 + krow) * 128 + j4]);
            *reinterpret_cast<float4*>(&Ws[krow][j4]) = v;
        }
        __syncthreads();

        #pragma unroll
        for (int k = 0; k < BK2; ++k) {
            float a[8], b[8];
            float4 a0 = *reinterpret_cast<const float4*>(&As[k][tRow * 8]);
            float4 a1 = *reinterpret_cast<const float4*>(&As[k][tRow * 8 + 4]);
            a[0]=a0.x; a[1]=a0.y; a[2]=a0.z; a[3]=a0.w;
            a[4]=a1.x; a[5]=a1.y; a[6]=a1.z; a[7]=a1.w;
            float4 b0 = *reinterpret_cast<const float4*>(&Ws[k][tCol * 8]);
            float4 b1 = *reinterpret_cast<const float4*>(&Ws[k][tCol * 8 + 4]);
            b[0]=b0.x; b[1]=b0.y; b[2]=b0.z; b[3]=b0.w;
            b[4]=b1.x; b[5]=b1.y; b[6]=b1.z; b[7]=b1.w;
            #pragma unroll
            for (int i = 0; i < 8; ++i)
                #pragma unroll
                for (int j = 0; j < 8; ++j)
                    acc[i][j] = fmaf(a[i], b[j], acc[i][j]);
        }
        __syncthreads();
    }

    const int ii   = tCol >> 2;
    const int mloc = (tCol & 3) * 8;

    #pragma unroll
    for (int i = 0; i < 8; ++i) {
        int r = mbase + tRow * 8 + i;
        float ss = 0.0f;
        #pragma unroll
        for (int j = 0; j < 8; ++j) ss = fmaf(acc[i][j], acc[i][j], ss);
        ss += __shfl_xor_sync(0xffffffffu, ss, 1);
        ss += __shfl_xor_sync(0xffffffffu, ss, 2);

        if (ii < 2) {
            float scale = rsqrtf(ss * (1.0f / 32.0f) + 1e-6f);
            float4 o0, o1;
            o0.x = acc[i][0] * scale; o0.y = acc[i][1] * scale;
            o0.z = acc[i][2] * scale; o0.w = acc[i][3] * scale;
            o1.x = acc[i][4] * scale; o1.y = acc[i][5] * scale;
            o1.z = acc[i][6] * scale; o1.w = acc[i][7] * scale;
            size_t base = (size_t)r * 256 + (size_t)c * 64 + ii * 32 + mloc;
            *reinterpret_cast<float4*>(&w1n_out[base])     = o0;
            *reinterpret_cast<float4*>(&w1n_out[base + 4]) = o1;
        } else {
            float4 o0, o1;
            o0.x = acc[i][0]; o0.y = acc[i][1];
            o0.z = acc[i][2]; o0.w = acc[i][3];
            o1.x = acc[i][4]; o1.y = acc[i][5];
            o1.z = acc[i][6]; o1.w = acc[i][7];
            size_t base = (size_t)r * 256 + (size_t)c * 64 + (ii - 2) * 32 + mloc;
            *reinterpret_cast<float4*>(&w2_out[base])     = o0;
            *reinterpret_cast<float4*>(&w2_out[base + 4]) = o1;
        }
    }
}

// ---------------------------------------------------------------------------
extern "C" void kernel_launch(void* const* d_in, const int* in_sizes, int n_in,
                              void* d_out, int out_size) {
    const float* query = (const float*)d_in[0];
    // d_in[1] = key_vec (unused by reference)
    const float* dw1   = (const float*)d_in[2];
    const float* qkw   = (const float*)d_in[3];
    const float* dd_p  = (const float*)d_in[4];

    float* out = (float*)d_out;
    float* w1n = out;
    float* w2  = out + W2_BASE;
    float* dd  = out + DD_BASE;

    cudaFuncSetAttribute(gemm1_mma, cudaFuncAttributeMaxDynamicSharedMemorySize, GEMM1_SMEM);

    conv_x<<<4096, 256>>>(reinterpret_cast<const float4*>(query));
    conv_w<<<dim3(NTOT / 32, DDIM / 32), dim3(32, 8)>>>(dw1, dd_p);
    gemm1_mma<<<dim3(5, 64), 256, GEMM1_SMEM>>>(dd);
    gemm2_rms<<<dim3(CNUM, 64), 256>>>(qkw, w1n, w2);
}

// round 4
// speedup vs baseline: 2.3667x; 1.1868x over previous
#include <cuda_runtime.h>
#include <cuda_bf16.h>
#include <cmath>
#include <cstdint>

// ---------------- problem constants ----------------
#define BT    8192
#define DDIM  4096
#define NH    512
#define NDD   128
#define NTOT  640
#define CNUM  4
#define KDIM  128

#define W2_BASE  (BT * CNUM * 2 * 32)   // 2,097,152
#define DD_BASE  (2 * W2_BASE)

// ---------------- device scratch ----------------
__device__ __nv_bfloat16 g_Whi[(size_t)NTOT * DDIM];   // [n][k]
__device__ __nv_bfloat16 g_Wlo[(size_t)NTOT * DDIM];
__device__ float g_hiddenT[(size_t)NH * BT];           // [col][row]

__device__ __forceinline__ float gelu_exact(float x) {
    return 0.5f * x * (1.0f + erff(x * 0.70710678118654752f));
}

#define CPA16(dst, src) \
    asm volatile("cp.async.cg.shared.global [%0], [%1], 16;" :: "r"(dst), "l"(src) : "memory")
#define CPA_COMMIT() asm volatile("cp.async.commit_group;" ::: "memory")
#define CPA_WAIT2()  asm volatile("cp.async.wait_group 2;" ::: "memory")

__device__ __forceinline__ uint32_t smem_u32(const void* p) {
    uint32_t a;
    asm("{ .reg .u64 t; cvta.to.shared.u64 t, %1; cvt.u32.u64 %0, t; }" : "=r"(a) : "l"(p));
    return a;
}

__device__ __forceinline__ void mma16816(float* d, const uint32_t* a, const uint32_t* b) {
    asm volatile(
        "mma.sync.aligned.m16n8k16.row.col.f32.bf16.bf16.f32 "
        "{%0,%1,%2,%3}, {%4,%5,%6,%7}, {%8,%9}, {%0,%1,%2,%3};"
        : "+f"(d[0]), "+f"(d[1]), "+f"(d[2]), "+f"(d[3])
        : "r"(a[0]), "r"(a[1]), "r"(a[2]), "r"(a[3]), "r"(b[0]), "r"(b[1]));
}

__device__ __forceinline__ void ldsm_x4(uint32_t addr, uint32_t* r) {
    asm volatile("ldmatrix.sync.aligned.m8n8.x4.shared.b16 {%0,%1,%2,%3}, [%4];"
        : "=r"(r[0]), "=r"(r[1]), "=r"(r[2]), "=r"(r[3]) : "r"(addr));
}

__device__ __forceinline__ uint32_t pack_hi2(float a, float b) {
    return (uint32_t)__bfloat16_as_ushort(__float2bfloat16_rn(a))
         | ((uint32_t)__bfloat16_as_ushort(__float2bfloat16_rn(b)) << 16);
}
__device__ __forceinline__ float bf_res(float x) {
    return x - __bfloat162float(__float2bfloat16_rn(x));
}

// ---------------------------------------------------------------------------
// conv_w: transpose+split [dw1 | dd_p] -> Whi/Wlo [640][4096] (K-major)
// ---------------------------------------------------------------------------
__global__ __launch_bounds__(256) void conv_w(const float* __restrict__ dw1,
                                              const float* __restrict__ ddp) {
    __shared__ float t[32][33];
    int n0 = blockIdx.x * 32, k0 = blockIdx.y * 32;
    int tx = threadIdx.x, ty = threadIdx.y;  // 32 x 8
    const float* src = (n0 < NH) ? dw1 : ddp;
    int ld   = (n0 < NH) ? NH : NDD;
    int ncol = (n0 < NH) ? (n0 + tx) : (n0 - NH + tx);
    #pragma unroll
    for (int j = 0; j < 4; ++j)
        t[ty + 8 * j][tx] = src[(size_t)(k0 + ty + 8 * j) * ld + ncol];
    __syncthreads();
    #pragma unroll
    for (int j = 0; j < 4; ++j) {
        int n = n0 + ty + 8 * j, k = k0 + tx;
        float v = t[tx][ty + 8 * j];
        __nv_bfloat16 h = __float2bfloat16_rn(v);
        g_Whi[(size_t)n * DDIM + k] = h;
        g_Wlo[(size_t)n * DDIM + k] = __float2bfloat16_rn(v - __bfloat162float(h));
    }
}

// ---------------------------------------------------------------------------
// gemm1_mma: [8192,4096] x [4096,640], 3-term bf16 split, in-kernel A split.
// CTA 128x128, BK=32, 3-stage pipeline, 2 CTAs/SM.
// Stage (32KB): [0,16K) A f32 staging -> converted in place to
//   Ahi [0,8K) + Alo [8K,16K) (64B rows, XOR swizzle); Whi [16K,24K); Wlo [24K,32K).
// Swizzle: 64B rows: chunk' = chunk ^ ((row>>1)&3); f32 128B rows: ch' = ch ^ (row&7).
// ---------------------------------------------------------------------------
#define STAGE_B 32768
#define STAGES  3
#define GEMM1_SMEM (STAGES * STAGE_B)   // 98304

__global__ __launch_bounds__(256, 2) void gemm1_mma(
    const float* __restrict__ X, float* __restrict__ dd_out) {
    extern __shared__ char smem[];
    uint32_t sb = smem_u32(smem);

    const int tid  = threadIdx.x;
    const int wid  = tid >> 5;
    const int lane = tid & 31;
    const int g    = lane >> 2;
    const int tg   = lane & 3;

    const int ntile = blockIdx.x;          // 0..4
    const int mbase = blockIdx.y << 7;
    const int m0w   = (wid & 1) * 64;
    const int n0w   = (wid >> 1) * 32;

    const float* Xrow = X + (size_t)mbase * DDIM;
    const __nv_bfloat16* Whrow = g_Whi + (size_t)(ntile * 128) * DDIM;
    const __nv_bfloat16* Wlrow = g_Wlo + (size_t)(ntile * 128) * DDIM;

    // refill geometry precompute
    // A f32: 4 chunks/thread; W: 2 chunks/thread each of hi/lo
    int aRow[4], aCh[4];
    #pragma unroll
    for (int q = 0; q < 4; ++q) { int cc = tid + q * 256; aRow[q] = cc >> 3; aCh[q] = cc & 7; }
    int wRow[2], wCh[2];
    #pragma unroll
    for (int q = 0; q < 2; ++q) { int cc = tid + q * 256; wRow[q] = cc >> 2; wCh[q] = cc & 3; }

    auto refill = [&](uint32_t stg, int k0) {
        #pragma unroll
        for (int q = 0; q < 4; ++q) {
            uint32_t dst = stg + aRow[q] * 128 + (uint32_t)((aCh[q] ^ (aRow[q] & 7)) << 4);
            CPA16(dst, Xrow + (size_t)aRow[q] * DDIM + k0 + aCh[q] * 4);
        }
        #pragma unroll
        for (int q = 0; q < 2; ++q) {
            uint32_t sw  = (uint32_t)((wCh[q] ^ ((wRow[q] >> 1) & 3)) << 4);
            uint32_t dst = stg + 16384 + wRow[q] * 64 + sw;
            const size_t so = (size_t)wRow[q] * DDIM + k0 + wCh[q] * 8;
            CPA16(dst, Whrow + so);
            CPA16(dst + 8192, Wlrow + so);
        }
    };

    // prologue
    #pragma unroll
    for (int s = 0; s < STAGES; ++s) { refill(sb + s * STAGE_B, s * 32); CPA_COMMIT(); }

    float acc[4][4][4];
    #pragma unroll
    for (int mi = 0; mi < 4; ++mi)
        #pragma unroll
        for (int ni = 0; ni < 4; ++ni)
            #pragma unroll
            for (int r = 0; r < 4; ++r) acc[mi][ni][r] = 0.0f;

    // conversion geometry
    const int cRow  = tid >> 1;
    const int cHalf = tid & 1;
    const int cFsw  = (cRow >> 1) & 3;

    // ldmatrix lane geometry
    const int rowAoff = ((lane >> 3) & 1) * 8 + (lane & 7);   // + mi*16 + m0w
    const int cAoff   = (lane >> 4) & 1;
    const int rowBoff = ((lane >> 4) & 1) * 8 + (lane & 7);   // + p*16 + n0w
    const int cBoff   = (lane >> 3) & 1;

    const int NKT = DDIM / 32;  // 128

    for (int it = 0; it < NKT; ++it) {
        int st = it % STAGES;
        uint32_t stg = sb + st * STAGE_B;
        CPA_WAIT2();
        __syncthreads();

        // ---- convert A f32 -> bf16 hi/lo in place ----
        uint4 v[4];
        {
            uint32_t fb = stg + cRow * 128;
            #pragma unroll
            for (int j = 0; j < 4; ++j) {
                uint32_t a = fb + (uint32_t)(((4 * cHalf + j) ^ (cRow & 7)) << 4);
                asm volatile("ld.shared.v4.u32 {%0,%1,%2,%3}, [%4];"
                    : "=r"(v[j].x), "=r"(v[j].y), "=r"(v[j].z), "=r"(v[j].w) : "r"(a));
            }
        }
        __syncthreads();
        {
            uint32_t hb = stg + cRow * 64;
            #pragma unroll
            for (int e = 0; e < 2; ++e) {
                float f[8];
                f[0] = __uint_as_float(v[2*e].x);   f[1] = __uint_as_float(v[2*e].y);
                f[2] = __uint_as_float(v[2*e].z);   f[3] = __uint_as_float(v[2*e].w);
                f[4] = __uint_as_float(v[2*e+1].x); f[5] = __uint_as_float(v[2*e+1].y);
                f[6] = __uint_as_float(v[2*e+1].z); f[7] = __uint_as_float(v[2*e+1].w);
                uint4 hh, ll;
                hh.x = pack_hi2(f[0], f[1]); hh.y = pack_hi2(f[2], f[3]);
                hh.z = pack_hi2(f[4], f[5]); hh.w = pack_hi2(f[6], f[7]);
                ll.x = pack_hi2(bf_res(f[0]), bf_res(f[1]));
                ll.y = pack_hi2(bf_res(f[2]), bf_res(f[3]));
                ll.z = pack_hi2(bf_res(f[4]), bf_res(f[5]));
                ll.w = pack_hi2(bf_res(f[6]), bf_res(f[7]));
                uint32_t off = (uint32_t)(((2 * cHalf + e) ^ cFsw) << 4);
                asm volatile("st.shared.v4.u32 [%0], {%1,%2,%3,%4};"
                    :: "r"(hb + off), "r"(hh.x), "r"(hh.y), "r"(hh.z), "r"(hh.w) : "memory");
                asm volatile("st.shared.v4.u32 [%0], {%1,%2,%3,%4};"
                    :: "r"(hb + 8192 + off), "r"(ll.x), "r"(ll.y), "r"(ll.z), "r"(ll.w) : "memory");
            }
        }
        __syncthreads();

        // ---- MMA phase ----
        #pragma unroll
        for (int ks = 0; ks < 2; ++ks) {
            int c0 = ks * 2;
            uint32_t bh[4][2], bl[4][2];
            #pragma unroll
            for (int p = 0; p < 2; ++p) {
                int rowB = n0w + p * 16 + rowBoff;
                int cB   = c0 + cBoff;
                uint32_t aW = stg + 16384 + rowB * 64
                            + (uint32_t)((cB ^ ((rowB >> 1) & 3)) << 4);
                uint32_t t[4];
                ldsm_x4(aW, t);
                bh[2*p][0] = t[0]; bh[2*p][1] = t[1];
                bh[2*p+1][0] = t[2]; bh[2*p+1][1] = t[3];
                ldsm_x4(aW + 8192, t);
                bl[2*p][0] = t[0]; bl[2*p][1] = t[1];
                bl[2*p+1][0] = t[2]; bl[2*p+1][1] = t[3];
            }
            #pragma unroll
            for (int mi = 0; mi < 4; ++mi) {
                int rowA = m0w + mi * 16 + rowAoff;
                int cA   = c0 + cAoff;
                uint32_t aA = stg + rowA * 64
                            + (uint32_t)((cA ^ ((rowA >> 1) & 3)) << 4);
                uint32_t ah[4], al[4];
                ldsm_x4(aA, ah);
                ldsm_x4(aA + 8192, al);
                #pragma unroll
                for (int ni = 0; ni < 4; ++ni) {
                    mma16816(acc[mi][ni], ah, bh[ni]);
                    mma16816(acc[mi][ni], ah, bl[ni]);
                    mma16816(acc[mi][ni], al, bh[ni]);
                }
            }
        }

        __syncthreads();
        if (it + STAGES < NKT) refill(stg, (it + STAGES) * 32);
        CPA_COMMIT();
    }

    // ---------------- epilogue ----------------
    if (ntile < 4) {
        __syncthreads();
        float* smT = reinterpret_cast<float*>(smem);   // [128 cols][136 rows]
        #pragma unroll
        for (int mi = 0; mi < 4; ++mi) {
            #pragma unroll
            for (int ni = 0; ni < 4; ++ni) {
                int row = m0w + mi * 16 + g;
                int col = n0w + ni * 8 + tg * 2;
                smT[(size_t)col * 136 + row]           = gelu_exact(acc[mi][ni][0]);
                smT[(size_t)(col + 1) * 136 + row]     = gelu_exact(acc[mi][ni][1]);
                smT[(size_t)col * 136 + row + 8]       = gelu_exact(acc[mi][ni][2]);
                smT[(size_t)(col + 1) * 136 + row + 8] = gelu_exact(acc[mi][ni][3]);
            }
        }
        __syncthreads();
        #pragma unroll
        for (int i = 0; i < 16; ++i) {
            int c   = tid + i * 256;
            int col = c >> 5;
            int rr  = (c & 31) << 2;
            float4 o;
            o.x = smT[(size_t)col * 136 + rr + 0];
            o.y = smT[(size_t)col * 136 + rr + 1];
            o.z = smT[(size_t)col * 136 + rr + 2];
            o.w = smT[(size_t)col * 136 + rr + 3];
            *reinterpret_cast<float4*>(
                &g_hiddenT[((size_t)(ntile * 128 + col) << 13) + mbase + rr]) = o;
        }
    } else {
        #pragma unroll
        for (int mi = 0; mi < 4; ++mi) {
            #pragma unroll
            for (int ni = 0; ni < 4; ++ni) {
                int row = mbase + m0w + mi * 16 + g;
                int col = n0w + ni * 8 + tg * 2;
                float2 o0 = make_float2(tanhf(acc[mi][ni][0]), tanhf(acc[mi][ni][1]));
                float2 o1 = make_float2(tanhf(acc[mi][ni][2]), tanhf(acc[mi][ni][3]));
                *reinterpret_cast<float2*>(&dd_out[(size_t)row * NDD + col])       = o0;
                *reinterpret_cast<float2*>(&dd_out[(size_t)(row + 8) * NDD + col]) = o1;
            }
        }
    }
}

// ---------------------------------------------------------------------------
// gemm2: per (row-tile, c): dw[128,128] = hiddenT chunk @ qkw[c]; RMS epilogue
// ---------------------------------------------------------------------------
#define BK2 16

__global__ __launch_bounds__(256) void gemm2_rms(
    const float* __restrict__ qkw,
    float* __restrict__ w1n_out,
    float* __restrict__ w2_out) {
    const int c     = blockIdx.x;
    const int mbase = blockIdx.y * 128;

    __shared__ float As[BK2][128];
    __shared__ float Ws[BK2][128];

    const int tx = threadIdx.x;
    const int tRow = tx >> 4, tCol = tx & 15;

    float acc[8][8];
    #pragma unroll
    for (int i = 0; i < 8; ++i)
        #pragma unroll
        for (int j = 0; j < 8; ++j) acc[i][j] = 0.0f;

    for (int k0 = 0; k0 < KDIM; k0 += BK2) {
        #pragma unroll
        for (int s = tx; s < 512; s += 256) {
            int k  = s >> 5;
            int r4 = (s & 31) << 2;
            float4 v = *reinterpret_cast<const float4*>(
                &g_hiddenT[((size_t)(c * KDIM + k0 + k) << 13) + mbase + r4]);
            *reinterpret_cast<float4*>(&As[k][r4]) = v;
        }
        #pragma unroll
        for (int s = tx; s < 512; s += 256) {
            int krow = s >> 5;
            int j4   = (s & 31) << 2;
            float4 v = *reinterpret_cast<const float4*>(
                &qkw[((size_t)c * KDIM + k0 + krow) * 128 + j4]);
            *reinterpret_cast<float4*>(&Ws[krow][j4]) = v;
        }
        __syncthreads();

        #pragma unroll
        for (int k = 0; k < BK2; ++k) {
            float a[8], b[8];
            float4 a0 = *reinterpret_cast<const float4*>(&As[k][tRow * 8]);
            float4 a1 = *reinterpret_cast<const float4*>(&As[k][tRow * 8 + 4]);
            a[0]=a0.x; a[1]=a0.y; a[2]=a0.z; a[3]=a0.w;
            a[4]=a1.x; a[5]=a1.y; a[6]=a1.z; a[7]=a1.w;
            float4 b0 = *reinterpret_cast<const float4*>(&Ws[k][tCol * 8]);
            float4 b1 = *reinterpret_cast<const float4*>(&Ws[k][tCol * 8 + 4]);
            b[0]=b0.x; b[1]=b0.y; b[2]=b0.z; b[3]=b0.w;
            b[4]=b1.x; b[5]=b1.y; b[6]=b1.z; b[7]=b1.w;
            #pragma unroll
            for (int i = 0; i < 8; ++i)
                #pragma unroll
                for (int j = 0; j < 8; ++j)
                    acc[i][j] = fmaf(a[i], b[j], acc[i][j]);
        }
        __syncthreads();
    }

    const int ii   = tCol >> 2;
    const int mloc = (tCol & 3) * 8;

    #pragma unroll
    for (int i = 0; i < 8; ++i) {
        int r = mbase + tRow * 8 + i;
        float ss = 0.0f;
        #pragma unroll
        for (int j = 0; j < 8; ++j) ss = fmaf(acc[i][j], acc[i][j], ss);
        ss += __shfl_xor_sync(0xffffffffu, ss, 1);
        ss += __shfl_xor_sync(0xffffffffu, ss, 2);

        if (ii < 2) {
            float scale = rsqrtf(ss * (1.0f / 32.0f) + 1e-6f);
            float4 o0, o1;
            o0.x = acc[i][0] * scale; o0.y = acc[i][1] * scale;
            o0.z = acc[i][2] * scale; o0.w = acc[i][3] * scale;
            o1.x = acc[i][4] * scale; o1.y = acc[i][5] * scale;
            o1.z = acc[i][6] * scale; o1.w = acc[i][7] * scale;
            size_t base = (size_t)r * 256 + (size_t)c * 64 + ii * 32 + mloc;
            *reinterpret_cast<float4*>(&w1n_out[base])     = o0;
            *reinterpret_cast<float4*>(&w1n_out[base + 4]) = o1;
        } else {
            float4 o0, o1;
            o0.x = acc[i][0]; o0.y = acc[i][1];
            o0.z = acc[i][2]; o0.w = acc[i][3];
            o1.x = acc[i][4]; o1.y = acc[i][5];
            o1.z = acc[i][6]; o1.w = acc[i][7];
            size_t base = (size_t)r * 256 + (size_t)c * 64 + (ii - 2) * 32 + mloc;
            *reinterpret_cast<float4*>(&w2_out[base])     = o0;
            *reinterpret_cast<float4*>(&w2_out[base + 4]) = o1;
        }
    }
}

// ---------------------------------------------------------------------------
extern "C" void kernel_launch(void* const* d_in, const int* in_sizes, int n_in,
                              void* d_out, int out_size) {
    const float* query = (const float*)d_in[0];
    // d_in[1] = key_vec (unused by reference)
    const float* dw1   = (const float*)d_in[2];
    const float* qkw   = (const float*)d_in[3];
    const float* dd_p  = (const float*)d_in[4];

    float* out = (float*)d_out;
    float* w1n = out;
    float* w2  = out + W2_BASE;
    float* dd  = out + DD_BASE;

    cudaFuncSetAttribute(gemm1_mma, cudaFuncAttributeMaxDynamicSharedMemorySize, GEMM1_SMEM);

    conv_w<<<dim3(NTOT / 32, DDIM / 32), dim3(32, 8)>>>(dw1, dd_p);
    gemm1_mma<<<dim3(5, 64), 256, GEMM1_SMEM>>>(query, dd);
    gemm2_rms<<<dim3(CNUM, 64), 256>>>(qkw, w1n, w2);
}

// round 5
// speedup vs baseline: 2.5023x; 1.0573x over previous
#include <cuda_runtime.h>
#include <cuda_bf16.h>
#include <cmath>
#include <cstdint>

// ---------------- problem constants ----------------
#define BT    8192
#define DDIM  4096
#define NH    512
#define NDD   128
#define NTOT  640
#define KDIM  128

#define W2_BASE  (BT * 4 * 2 * 32)   // 2,097,152
#define DD_BASE  (2 * W2_BASE)

// ---------------- device scratch ----------------
__device__ __nv_bfloat16 g_Whi[(size_t)NTOT * DDIM];   // [n][k]
__device__ __nv_bfloat16 g_Wlo[(size_t)NTOT * DDIM];
__device__ __nv_bfloat16 g_Qhi[4 * KDIM * KDIM];       // qkwT split: [c][j][k]
__device__ __nv_bfloat16 g_Qlo[4 * KDIM * KDIM];

__device__ __forceinline__ float gelu_exact(float x) {
    return 0.5f * x * (1.0f + erff(x * 0.70710678118654752f));
}

#define CPA16(dst, src) \
    asm volatile("cp.async.cg.shared.global [%0], [%1], 16;" :: "r"(dst), "l"(src) : "memory")
#define CPA_COMMIT() asm volatile("cp.async.commit_group;" ::: "memory")
#define CPA_WAIT2()  asm volatile("cp.async.wait_group 2;" ::: "memory")
#define CPA_WAIT0()  asm volatile("cp.async.wait_group 0;" ::: "memory")

__device__ __forceinline__ uint32_t smem_u32(const void* p) {
    uint32_t a;
    asm("{ .reg .u64 t; cvta.to.shared.u64 t, %1; cvt.u32.u64 %0, t; }" : "=r"(a) : "l"(p));
    return a;
}

__device__ __forceinline__ void mma16816(float* d, const uint32_t* a, const uint32_t* b) {
    asm volatile(
        "mma.sync.aligned.m16n8k16.row.col.f32.bf16.bf16.f32 "
        "{%0,%1,%2,%3}, {%4,%5,%6,%7}, {%8,%9}, {%0,%1,%2,%3};"
        : "+f"(d[0]), "+f"(d[1]), "+f"(d[2]), "+f"(d[3])
        : "r"(a[0]), "r"(a[1]), "r"(a[2]), "r"(a[3]), "r"(b[0]), "r"(b[1]));
}

__device__ __forceinline__ void ldsm_x4(uint32_t addr, uint32_t* r) {
    asm volatile("ldmatrix.sync.aligned.m8n8.x4.shared.b16 {%0,%1,%2,%3}, [%4];"
        : "=r"(r[0]), "=r"(r[1]), "=r"(r[2]), "=r"(r[3]) : "r"(addr));
}

__device__ __forceinline__ uint32_t pack_hi2(float a, float b) {
    return (uint32_t)__bfloat16_as_ushort(__float2bfloat16_rn(a))
         | ((uint32_t)__bfloat16_as_ushort(__float2bfloat16_rn(b)) << 16);
}
__device__ __forceinline__ float bf_res(float x) {
    return x - __bfloat162float(__float2bfloat16_rn(x));
}

// ---------------------------------------------------------------------------
// conv_w: transpose+split [dw1 | dd_p] -> Whi/Wlo [640][4096] (K-major)
// ---------------------------------------------------------------------------
__global__ __launch_bounds__(256) void conv_w(const float* __restrict__ dw1,
                                              const float* __restrict__ ddp) {
    __shared__ float t[32][33];
    int n0 = blockIdx.x * 32, k0 = blockIdx.y * 32;
    int tx = threadIdx.x, ty = threadIdx.y;
    const float* src = (n0 < NH) ? dw1 : ddp;
    int ld   = (n0 < NH) ? NH : NDD;
    int ncol = (n0 < NH) ? (n0 + tx) : (n0 - NH + tx);
    #pragma unroll
    for (int j = 0; j < 4; ++j)
        t[ty + 8 * j][tx] = src[(size_t)(k0 + ty + 8 * j) * ld + ncol];
    __syncthreads();
    #pragma unroll
    for (int j = 0; j < 4; ++j) {
        int n = n0 + ty + 8 * j, k = k0 + tx;
        float v = t[tx][ty + 8 * j];
        __nv_bfloat16 h = __float2bfloat16_rn(v);
        g_Whi[(size_t)n * DDIM + k] = h;
        g_Wlo[(size_t)n * DDIM + k] = __float2bfloat16_rn(v - __bfloat162float(h));
    }
}

// ---------------------------------------------------------------------------
// conv_q: transpose+split qkw [c][k][j] -> Qhi/Qlo [c][j][k]
// ---------------------------------------------------------------------------
__global__ __launch_bounds__(256) void conv_q(const float* __restrict__ qkw) {
    __shared__ float t[32][33];
    int c = blockIdx.x, j0 = blockIdx.y * 32, k0 = blockIdx.z * 32;
    int tx = threadIdx.x, ty = threadIdx.y;
    #pragma unroll
    for (int jj = 0; jj < 4; ++jj)
        t[ty + 8 * jj][tx] = qkw[((c * KDIM) + (k0 + ty + 8 * jj)) * KDIM + j0 + tx];
    __syncthreads();
    #pragma unroll
    for (int jj = 0; jj < 4; ++jj) {
        int j = j0 + ty + 8 * jj, k = k0 + tx;
        float v = t[tx][ty + 8 * jj];
        __nv_bfloat16 h = __float2bfloat16_rn(v);
        g_Qhi[(c * KDIM + j) * KDIM + k] = h;
        g_Qlo[(c * KDIM + j) * KDIM + k] = __float2bfloat16_rn(v - __bfloat162float(h));
    }
}

// ---------------------------------------------------------------------------
// gemm1_mma: [8192,4096] x [4096,640], 3-term bf16 split, LDG->reg cvt.
// CTA 128x128, BK=32, A double-buffered bf16 (2x16K), W 4-stage cp.async (4x16K),
// 96KB smem, 2 CTAs/SM, one __syncthreads per iter.
// ntile<4: fused gemm2 epilogue (gelu -> smem bf16 split -> MMA w/ qkwT -> RMS -> out).
// ntile==4: tanh -> dd direct stores.
// ---------------------------------------------------------------------------
#define ABUF_B  16384
#define WST_B   16384
#define W_OFF   32768
#define GEMM1_SMEM 98304

__global__ __launch_bounds__(256, 2) void gemm1_mma(
    const float* __restrict__ X,
    float* __restrict__ w1n_out, float* __restrict__ w2_out,
    float* __restrict__ dd_out) {
    extern __shared__ char smem[];
    uint32_t sb = smem_u32(smem);

    const int tid  = threadIdx.x;
    const int wid  = tid >> 5;
    const int lane = tid & 31;
    const int g    = lane >> 3;            // unused placeholder
    (void)g;
    const int gq   = lane >> 2;            // quad-group 0..7
    const int tg   = lane & 3;

    const int ntile = blockIdx.x;          // 0..4
    const int mbase = blockIdx.y << 7;
    const int m0w   = (wid & 1) * 64;
    const int n0w   = (wid >> 1) * 32;

    const float* Xrow = X + (size_t)mbase * DDIM;
    const __nv_bfloat16* Whrow = g_Whi + (size_t)(ntile * 128) * DDIM;
    const __nv_bfloat16* Wlrow = g_Wlo + (size_t)(ntile * 128) * DDIM;

    // A LDG geometry: 4 chunks of 16B f32 per thread (128 rows x 32 k f32)
    int aRow[4], aCh[4];
    uint32_t aSts[4];
    #pragma unroll
    for (int q = 0; q < 4; ++q) {
        int cc = tid + q * 256;
        aRow[q] = cc >> 3; aCh[q] = cc & 7;
        aSts[q] = (uint32_t)(aRow[q] * 64
                + ((((aCh[q] >> 1) ^ ((aRow[q] >> 1) & 3)) << 4) + ((aCh[q] & 1) << 3)));
    }
    // W cp.async geometry
    int wRow[2], wCh[2];
    #pragma unroll
    for (int q = 0; q < 2; ++q) { int cc = tid + q * 256; wRow[q] = cc >> 2; wCh[q] = cc & 3; }

    auto w_refill = [&](uint32_t stg, int k0) {
        #pragma unroll
        for (int q = 0; q < 2; ++q) {
            uint32_t dst = stg + wRow[q] * 64
                         + (uint32_t)((wCh[q] ^ ((wRow[q] >> 1) & 3)) << 4);
            const size_t so = (size_t)wRow[q] * DDIM + k0 + wCh[q] * 8;
            CPA16(dst, Whrow + so);
            CPA16(dst + 8192, Wlrow + so);
        }
    };

    float4 xreg[4];
    auto a_ldg = [&](int k0) {
        #pragma unroll
        for (int q = 0; q < 4; ++q)
            xreg[q] = *reinterpret_cast<const float4*>(
                &Xrow[(size_t)aRow[q] * DDIM + k0 + aCh[q] * 4]);
    };
    auto a_sts = [&](uint32_t abuf) {
        #pragma unroll
        for (int q = 0; q < 4; ++q) {
            float4 v = xreg[q];
            uint32_t h0 = pack_hi2(v.x, v.y), h1 = pack_hi2(v.z, v.w);
            uint32_t l0 = pack_hi2(bf_res(v.x), bf_res(v.y));
            uint32_t l1 = pack_hi2(bf_res(v.z), bf_res(v.w));
            uint32_t a = abuf + aSts[q];
            asm volatile("st.shared.v2.u32 [%0], {%1,%2};" :: "r"(a), "r"(h0), "r"(h1) : "memory");
            asm volatile("st.shared.v2.u32 [%0], {%1,%2};" :: "r"(a + 8192), "r"(l0), "r"(l1) : "memory");
        }
    };

    // ldmatrix lane geometry
    const int rowAoff = ((lane >> 3) & 1) * 8 + (lane & 7);
    const int cAoff   = (lane >> 4) & 1;
    const int rowBoff = ((lane >> 4) & 1) * 8 + (lane & 7);
    const int cBoff   = (lane >> 3) & 1;

    // ---- prologue ----
    a_ldg(0);
    a_sts(sb);           // Abuf[0]
    a_ldg(32);           // for iter 1
    w_refill(sb + W_OFF, 0);            CPA_COMMIT();
    w_refill(sb + W_OFF + WST_B, 32);   CPA_COMMIT();
    w_refill(sb + W_OFF + 2 * WST_B, 64); CPA_COMMIT();

    float acc[4][4][4];
    #pragma unroll
    for (int mi = 0; mi < 4; ++mi)
        #pragma unroll
        for (int ni = 0; ni < 4; ++ni)
            #pragma unroll
            for (int r = 0; r < 4; ++r) acc[mi][ni][r] = 0.0f;

    const int NKT = DDIM / 32;  // 128

    for (int it = 0; it < NKT; ++it) {
        uint32_t abuf = sb + (uint32_t)(it & 1) * ABUF_B;
        uint32_t wstg = sb + W_OFF + (uint32_t)(it & 3) * WST_B;

        CPA_WAIT2();
        __syncthreads();

        if (it + 1 < NKT) a_sts(sb + (uint32_t)((it + 1) & 1) * ABUF_B);
        if (it + 2 < NKT) a_ldg((it + 2) * 32);

        #pragma unroll
        for (int ks = 0; ks < 2; ++ks) {
            int c0 = ks * 2;
            uint32_t bh[4][2], bl[4][2];
            #pragma unroll
            for (int p = 0; p < 2; ++p) {
                int rowB = n0w + p * 16 + rowBoff;
                int cB   = c0 + cBoff;
                uint32_t aW = wstg + rowB * 64
                            + (uint32_t)((cB ^ ((rowB >> 1) & 3)) << 4);
                uint32_t t[4];
                ldsm_x4(aW, t);
                bh[2*p][0] = t[0]; bh[2*p][1] = t[1];
                bh[2*p+1][0] = t[2]; bh[2*p+1][1] = t[3];
                ldsm_x4(aW + 8192, t);
                bl[2*p][0] = t[0]; bl[2*p][1] = t[1];
                bl[2*p+1][0] = t[2]; bl[2*p+1][1] = t[3];
            }
            #pragma unroll
            for (int mi = 0; mi < 4; ++mi) {
                int rowA = m0w + mi * 16 + rowAoff;
                int cA   = c0 + cAoff;
                uint32_t aA = abuf + rowA * 64
                            + (uint32_t)((cA ^ ((rowA >> 1) & 3)) << 4);
                uint32_t ah[4], al[4];
                ldsm_x4(aA, ah);
                ldsm_x4(aA + 8192, al);
                #pragma unroll
                for (int ni = 0; ni < 4; ++ni) {
                    mma16816(acc[mi][ni], ah, bh[ni]);
                    mma16816(acc[mi][ni], ah, bl[ni]);
                    mma16816(acc[mi][ni], al, bh[ni]);
                }
            }
        }

        if (it + 3 < NKT)
            w_refill(sb + W_OFF + (uint32_t)((it + 3) & 3) * WST_B, (it + 3) * 32);
        CPA_COMMIT();
    }

    CPA_WAIT0();
    __syncthreads();

    // ================= epilogue =================
    if (ntile == 4) {
        // dd: tanh, direct row-major stores
        #pragma unroll
        for (int mi = 0; mi < 4; ++mi) {
            #pragma unroll
            for (int ni = 0; ni < 4; ++ni) {
                int row = mbase + m0w + mi * 16 + gq;
                int col = n0w + ni * 8 + tg * 2;
                float2 o0 = make_float2(tanhf(acc[mi][ni][0]), tanhf(acc[mi][ni][1]));
                float2 o1 = make_float2(tanhf(acc[mi][ni][2]), tanhf(acc[mi][ni][3]));
                *reinterpret_cast<float2*>(&dd_out[(size_t)row * NDD + col])       = o0;
                *reinterpret_cast<float2*>(&dd_out[(size_t)(row + 8) * NDD + col]) = o1;
            }
        }
        return;
    }

    const int c = ntile;

    // Phase 1: gelu -> bf16 split into A region:
    //   hi at sb[0,32K): rows 256B, 16 chunks, swizzle ch ^ (row&7); lo at +32K.
    #pragma unroll
    for (int mi = 0; mi < 4; ++mi) {
        #pragma unroll
        for (int ni = 0; ni < 4; ++ni) {
            int row0 = m0w + mi * 16 + gq;
            int col  = n0w + ni * 8 + tg * 2;
            uint32_t ch  = (uint32_t)(col >> 3);
            uint32_t wi  = (uint32_t)((col & 7) * 2);
            #pragma unroll
            for (int r2 = 0; r2 < 2; ++r2) {
                int row = row0 + r2 * 8;
                float v0 = gelu_exact(acc[mi][ni][2 * r2 + 0]);
                float v1 = gelu_exact(acc[mi][ni][2 * r2 + 1]);
                uint32_t h = pack_hi2(v0, v1);
                uint32_t l = pack_hi2(bf_res(v0), bf_res(v1));
                uint32_t a = sb + row * 256 + ((ch ^ (uint32_t)(row & 7)) << 4) + wi;
                asm volatile("st.shared.u32 [%0], %1;" :: "r"(a), "r"(h) : "memory");
                asm volatile("st.shared.u32 [%0], %1;" :: "r"(a + 32768), "r"(l) : "memory");
            }
        }
    }

    // Phase 2: 128x128x128 3-term MMA with qkwT[c] (2 k-halves of 64)
    float acc2[4][4][4];
    #pragma unroll
    for (int mi = 0; mi < 4; ++mi)
        #pragma unroll
        for (int ni = 0; ni < 4; ++ni)
            #pragma unroll
            for (int r = 0; r < 4; ++r) acc2[mi][ni][r] = 0.0f;

    const uint32_t wb = sb + 65536;   // W region: hi 16K, lo 16K
    for (int kb = 0; kb < 2; ++kb) {
        __syncthreads();   // phase-1 STS visible (kb=0) / previous-half reads done (kb=1)
        #pragma unroll
        for (int q = 0; q < 4; ++q) {
            int cc = tid + q * 256;
            int j  = cc >> 3, ch = cc & 7;
            uint32_t dst = wb + j * 128 + (uint32_t)((ch ^ (j & 7)) << 4);
            size_t so = ((size_t)(c * KDIM + j)) * KDIM + kb * 64 + ch * 8;
            CPA16(dst, g_Qhi + so);
            CPA16(dst + 16384, g_Qlo + so);
        }
        CPA_COMMIT();
        CPA_WAIT0();
        __syncthreads();

        #pragma unroll
        for (int ksl = 0; ksl < 4; ++ksl) {
            uint32_t bh[4][2], bl[4][2];
            #pragma unroll
            for (int p = 0; p < 2; ++p) {
                int rowB = n0w + p * 16 + rowBoff;
                int cB   = ksl * 2 + cBoff;
                uint32_t aW = wb + rowB * 128
                            + (uint32_t)((cB ^ (rowB & 7)) << 4);
                uint32_t t[4];
                ldsm_x4(aW, t);
                bh[2*p][0] = t[0]; bh[2*p][1] = t[1];
                bh[2*p+1][0] = t[2]; bh[2*p+1][1] = t[3];
                ldsm_x4(aW + 16384, t);
                bl[2*p][0] = t[0]; bl[2*p][1] = t[1];
                bl[2*p+1][0] = t[2]; bl[2*p+1][1] = t[3];
            }
            #pragma unroll
            for (int mi = 0; mi < 4; ++mi) {
                int rowA = m0w + mi * 16 + rowAoff;
                int cA   = kb * 8 + ksl * 2 + cAoff;
                uint32_t aA = sb + rowA * 256
                            + (uint32_t)((cA ^ (rowA & 7)) << 4);
                uint32_t ah[4], al[4];
                ldsm_x4(aA, ah);
                ldsm_x4(aA + 32768, al);
                #pragma unroll
                for (int ni = 0; ni < 4; ++ni) {
                    mma16816(acc2[mi][ni], ah, bh[ni]);
                    mma16816(acc2[mi][ni], ah, bl[ni]);
                    mma16816(acc2[mi][ni], al, bh[ni]);
                }
            }
        }
    }

    // Phase 3: RMS over M=32 (warp's 32 cols = one ii group) + stores
    const int ii = n0w >> 5;
    #pragma unroll
    for (int mi = 0; mi < 4; ++mi) {
        int row0 = m0w + mi * 16 + gq;
        #pragma unroll
        for (int r2 = 0; r2 < 2; ++r2) {
            int r = mbase + row0 + r2 * 8;
            float ss = 0.0f;
            #pragma unroll
            for (int ni = 0; ni < 4; ++ni) {
                ss = fmaf(acc2[mi][ni][2*r2+0], acc2[mi][ni][2*r2+0], ss);
                ss = fmaf(acc2[mi][ni][2*r2+1], acc2[mi][ni][2*r2+1], ss);
            }
            ss += __shfl_xor_sync(0xffffffffu, ss, 1);
            ss += __shfl_xor_sync(0xffffffffu, ss, 2);

            if (ii < 2) {
                float scale = rsqrtf(ss * (1.0f / 32.0f) + 1e-6f);
                #pragma unroll
                for (int ni = 0; ni < 4; ++ni) {
                    int m = (n0w & 31) + ni * 8 + tg * 2;
                    float2 o = make_float2(acc2[mi][ni][2*r2+0] * scale,
                                           acc2[mi][ni][2*r2+1] * scale);
                    *reinterpret_cast<float2*>(
                        &w1n_out[(size_t)r * 256 + c * 64 + ii * 32 + m]) = o;
                }
            } else {
                #pragma unroll
                for (int ni = 0; ni < 4; ++ni) {
                    int m = (n0w & 31) + ni * 8 + tg * 2;
                    float2 o = make_float2(acc2[mi][ni][2*r2+0],
                                           acc2[mi][ni][2*r2+1]);
                    *reinterpret_cast<float2*>(
                        &w2_out[(size_t)r * 256 + c * 64 + (ii - 2) * 32 + m]) = o;
                }
            }
        }
    }
}

// ---------------------------------------------------------------------------
extern "C" void kernel_launch(void* const* d_in, const int* in_sizes, int n_in,
                              void* d_out, int out_size) {
    const float* query = (const float*)d_in[0];
    // d_in[1] = key_vec (unused by reference)
    const float* dw1   = (const float*)d_in[2];
    const float* qkw   = (const float*)d_in[3];
    const float* dd_p  = (const float*)d_in[4];

    float* out = (float*)d_out;
    float* w1n = out;
    float* w2  = out + W2_BASE;
    float* dd  = out + DD_BASE;

    cudaFuncSetAttribute(gemm1_mma, cudaFuncAttributeMaxDynamicSharedMemorySize, GEMM1_SMEM);

    conv_w<<<dim3(NTOT / 32, DDIM / 32), dim3(32, 8)>>>(dw1, dd_p);
    conv_q<<<dim3(4, 4, 4), dim3(32, 8)>>>(qkw);
    gemm1_mma<<<dim3(5, 64), 256, GEMM1_SMEM>>>(query, w1n, w2, dd);
}

// round 6
// speedup vs baseline: 3.6153x; 1.4448x over previous
#include <cuda_runtime.h>
#include <cuda_fp16.h>
#include <cmath>
#include <cstdint>

// ---------------- problem constants ----------------
#define BT    8192
#define DDIM  4096
#define NH    512
#define NDD   128
#define NTOT  640
#define KDIM  128

#define W2_BASE  (BT * 4 * 2 * 32)   // 2,097,152
#define DD_BASE  (2 * W2_BASE)

// ---------------- device scratch ----------------
__device__ __half g_Wh[(size_t)NTOT * DDIM];      // [n][k] fp16 (single term)
__device__ __half g_Qhi[4 * KDIM * KDIM];         // qkwT split: [c][j][k]
__device__ __half g_Qlo[4 * KDIM * KDIM];

__device__ __forceinline__ float gelu_exact(float x) {
    return 0.5f * x * (1.0f + erff(x * 0.70710678118654752f));
}

#define CPA16(dst, src) \
    asm volatile("cp.async.cg.shared.global [%0], [%1], 16;" :: "r"(dst), "l"(src) : "memory")
#define CPA_COMMIT() asm volatile("cp.async.commit_group;" ::: "memory")
#define CPA_WAIT2()  asm volatile("cp.async.wait_group 2;" ::: "memory")
#define CPA_WAIT0()  asm volatile("cp.async.wait_group 0;" ::: "memory")

__device__ __forceinline__ uint32_t smem_u32(const void* p) {
    uint32_t a;
    asm("{ .reg .u64 t; cvta.to.shared.u64 t, %1; cvt.u32.u64 %0, t; }" : "=r"(a) : "l"(p));
    return a;
}

__device__ __forceinline__ void mma16816(float* d, const uint32_t* a, const uint32_t* b) {
    asm volatile(
        "mma.sync.aligned.m16n8k16.row.col.f32.f16.f16.f32 "
        "{%0,%1,%2,%3}, {%4,%5,%6,%7}, {%8,%9}, {%0,%1,%2,%3};"
        : "+f"(d[0]), "+f"(d[1]), "+f"(d[2]), "+f"(d[3])
        : "r"(a[0]), "r"(a[1]), "r"(a[2]), "r"(a[3]), "r"(b[0]), "r"(b[1]));
}

__device__ __forceinline__ void ldsm_x4(uint32_t addr, uint32_t* r) {
    asm volatile("ldmatrix.sync.aligned.m8n8.x4.shared.b16 {%0,%1,%2,%3}, [%4];"
        : "=r"(r[0]), "=r"(r[1]), "=r"(r[2]), "=r"(r[3]) : "r"(addr));
}

__device__ __forceinline__ uint32_t pack_h2(float a, float b) {
    __half2 h = __floats2half2_rn(a, b);
    return *reinterpret_cast<uint32_t*>(&h);
}
__device__ __forceinline__ float h_res(float x) {
    return x - __half2float(__float2half_rn(x));
}

// ---------------------------------------------------------------------------
// conv_w: transpose [dw1 | dd_p] -> Wh [640][4096] fp16 (K-major)
// ---------------------------------------------------------------------------
__global__ __launch_bounds__(256) void conv_w(const float* __restrict__ dw1,
                                              const float* __restrict__ ddp) {
    __shared__ float t[32][33];
    int n0 = blockIdx.x * 32, k0 = blockIdx.y * 32;
    int tx = threadIdx.x, ty = threadIdx.y;
    const float* src = (n0 < NH) ? dw1 : ddp;
    int ld   = (n0 < NH) ? NH : NDD;
    int ncol = (n0 < NH) ? (n0 + tx) : (n0 - NH + tx);
    #pragma unroll
    for (int j = 0; j < 4; ++j)
        t[ty + 8 * j][tx] = src[(size_t)(k0 + ty + 8 * j) * ld + ncol];
    __syncthreads();
    #pragma unroll
    for (int j = 0; j < 4; ++j) {
        int n = n0 + ty + 8 * j, k = k0 + tx;
        g_Wh[(size_t)n * DDIM + k] = __float2half_rn(t[tx][ty + 8 * j]);
    }
}

// ---------------------------------------------------------------------------
// conv_q: transpose+split qkw [c][k][j] -> Qhi/Qlo [c][j][k] fp16
// ---------------------------------------------------------------------------
__global__ __launch_bounds__(256) void conv_q(const float* __restrict__ qkw) {
    __shared__ float t[32][33];
    int c = blockIdx.x, j0 = blockIdx.y * 32, k0 = blockIdx.z * 32;
    int tx = threadIdx.x, ty = threadIdx.y;
    #pragma unroll
    for (int jj = 0; jj < 4; ++jj)
        t[ty + 8 * jj][tx] = qkw[((c * KDIM) + (k0 + ty + 8 * jj)) * KDIM + j0 + tx];
    __syncthreads();
    #pragma unroll
    for (int jj = 0; jj < 4; ++jj) {
        int j = j0 + ty + 8 * jj, k = k0 + tx;
        float v = t[tx][ty + 8 * jj];
        __half h = __float2half_rn(v);
        g_Qhi[(c * KDIM + j) * KDIM + k] = h;
        g_Qlo[(c * KDIM + j) * KDIM + k] = __float2half_rn(v - __half2float(h));
    }
}

// ---------------------------------------------------------------------------
// gemm1_mma: [8192,4096] x [4096,640], fp16 2-term split (ah*wh + al*wh).
// CTA 128x128, BK=32, A double-buffered fp16 hi+lo (2x16K), W 4-stage (4x8K),
// 96KB smem (epilogue needs it), 2 CTAs/SM, one __syncthreads per iter.
// ntile<4: fused second-GEMM epilogue (gelu -> fp16 split -> 3-term MMA with
// qkwT -> RMS -> w1n/w2). ntile==4: tanh -> dd.
// ---------------------------------------------------------------------------
#define ABUF_B  16384
#define WST_B   8192
#define W_OFF   32768
#define GEMM1_SMEM 98304

__global__ __launch_bounds__(256, 2) void gemm1_mma(
    const float* __restrict__ X,
    float* __restrict__ w1n_out, float* __restrict__ w2_out,
    float* __restrict__ dd_out) {
    extern __shared__ char smem[];
    uint32_t sb = smem_u32(smem);

    const int tid  = threadIdx.x;
    const int wid  = tid >> 5;
    const int lane = tid & 31;
    const int gq   = lane >> 2;
    const int tg   = lane & 3;

    const int ntile = blockIdx.x;          // 0..4
    const int mbase = blockIdx.y << 7;
    const int m0w   = (wid & 1) * 64;
    const int n0w   = (wid >> 1) * 32;

    const float* Xrow = X + (size_t)mbase * DDIM;
    const __half* Whrow = g_Wh + (size_t)(ntile * 128) * DDIM;

    // A LDG geometry: 4 chunks of 16B f32 per thread (128 rows x 32 k f32)
    int aRow[4], aCh[4];
    uint32_t aSts[4];
    #pragma unroll
    for (int q = 0; q < 4; ++q) {
        int cc = tid + q * 256;
        aRow[q] = cc >> 3; aCh[q] = cc & 7;
        aSts[q] = (uint32_t)(aRow[q] * 64
                + ((((aCh[q] >> 1) ^ ((aRow[q] >> 1) & 3)) << 4) + ((aCh[q] & 1) << 3)));
    }
    // W cp.async geometry: 8KB/stage -> 2 chunks of 16B per thread
    int wRow[2], wCh[2];
    #pragma unroll
    for (int q = 0; q < 2; ++q) { int cc = tid + q * 256; wRow[q] = cc >> 2; wCh[q] = cc & 3; }

    auto w_refill = [&](uint32_t stg, int k0) {
        #pragma unroll
        for (int q = 0; q < 2; ++q) {
            uint32_t dst = stg + wRow[q] * 64
                         + (uint32_t)((wCh[q] ^ ((wRow[q] >> 1) & 3)) << 4);
            CPA16(dst, Whrow + (size_t)wRow[q] * DDIM + k0 + wCh[q] * 8);
        }
    };

    float4 xreg[4];
    auto a_ldg = [&](int k0) {
        #pragma unroll
        for (int q = 0; q < 4; ++q)
            xreg[q] = *reinterpret_cast<const float4*>(
                &Xrow[(size_t)aRow[q] * DDIM + k0 + aCh[q] * 4]);
    };
    auto a_sts = [&](uint32_t abuf) {
        #pragma unroll
        for (int q = 0; q < 4; ++q) {
            float4 v = xreg[q];
            uint32_t h0 = pack_h2(v.x, v.y), h1 = pack_h2(v.z, v.w);
            uint32_t l0 = pack_h2(h_res(v.x), h_res(v.y));
            uint32_t l1 = pack_h2(h_res(v.z), h_res(v.w));
            uint32_t a = abuf + aSts[q];
            asm volatile("st.shared.v2.u32 [%0], {%1,%2};" :: "r"(a), "r"(h0), "r"(h1) : "memory");
            asm volatile("st.shared.v2.u32 [%0], {%1,%2};" :: "r"(a + 8192), "r"(l0), "r"(l1) : "memory");
        }
    };

    // ldmatrix lane geometry
    const int rowAoff = ((lane >> 3) & 1) * 8 + (lane & 7);
    const int cAoff   = (lane >> 4) & 1;
    const int rowBoff = ((lane >> 4) & 1) * 8 + (lane & 7);
    const int cBoff   = (lane >> 3) & 1;

    // ---- prologue ----
    a_ldg(0);
    a_sts(sb);
    a_ldg(32);
    w_refill(sb + W_OFF, 0);              CPA_COMMIT();
    w_refill(sb + W_OFF + WST_B, 32);     CPA_COMMIT();
    w_refill(sb + W_OFF + 2 * WST_B, 64); CPA_COMMIT();

    float acc[4][4][4];
    #pragma unroll
    for (int mi = 0; mi < 4; ++mi)
        #pragma unroll
        for (int ni = 0; ni < 4; ++ni)
            #pragma unroll
            for (int r = 0; r < 4; ++r) acc[mi][ni][r] = 0.0f;

    const int NKT = DDIM / 32;  // 128

    for (int it = 0; it < NKT; ++it) {
        uint32_t abuf = sb + (uint32_t)(it & 1) * ABUF_B;
        uint32_t wstg = sb + W_OFF + (uint32_t)(it & 3) * WST_B;

        CPA_WAIT2();
        __syncthreads();

        if (it + 1 < NKT) a_sts(sb + (uint32_t)((it + 1) & 1) * ABUF_B);
        if (it + 2 < NKT) a_ldg((it + 2) * 32);

        #pragma unroll
        for (int ks = 0; ks < 2; ++ks) {
            int c0 = ks * 2;
            uint32_t bh[4][2];
            #pragma unroll
            for (int p = 0; p < 2; ++p) {
                int rowB = n0w + p * 16 + rowBoff;
                int cB   = c0 + cBoff;
                uint32_t aW = wstg + rowB * 64
                            + (uint32_t)((cB ^ ((rowB >> 1) & 3)) << 4);
                uint32_t t[4];
                ldsm_x4(aW, t);
                bh[2*p][0] = t[0]; bh[2*p][1] = t[1];
                bh[2*p+1][0] = t[2]; bh[2*p+1][1] = t[3];
            }
            #pragma unroll
            for (int mi = 0; mi < 4; ++mi) {
                int rowA = m0w + mi * 16 + rowAoff;
                int cA   = c0 + cAoff;
                uint32_t aA = abuf + rowA * 64
                            + (uint32_t)((cA ^ ((rowA >> 1) & 3)) << 4);
                uint32_t ah[4], al[4];
                ldsm_x4(aA, ah);
                ldsm_x4(aA + 8192, al);
                #pragma unroll
                for (int ni = 0; ni < 4; ++ni) {
                    mma16816(acc[mi][ni], ah, bh[ni]);
                    mma16816(acc[mi][ni], al, bh[ni]);
                }
            }
        }

        if (it + 3 < NKT)
            w_refill(sb + W_OFF + (uint32_t)((it + 3) & 3) * WST_B, (it + 3) * 32);
        CPA_COMMIT();
    }

    CPA_WAIT0();
    __syncthreads();

    // ================= epilogue =================
    if (ntile == 4) {
        #pragma unroll
        for (int mi = 0; mi < 4; ++mi) {
            #pragma unroll
            for (int ni = 0; ni < 4; ++ni) {
                int row = mbase + m0w + mi * 16 + gq;
                int col = n0w + ni * 8 + tg * 2;
                float2 o0 = make_float2(tanhf(acc[mi][ni][0]), tanhf(acc[mi][ni][1]));
                float2 o1 = make_float2(tanhf(acc[mi][ni][2]), tanhf(acc[mi][ni][3]));
                *reinterpret_cast<float2*>(&dd_out[(size_t)row * NDD + col])       = o0;
                *reinterpret_cast<float2*>(&dd_out[(size_t)(row + 8) * NDD + col]) = o1;
            }
        }
        return;
    }

    const int c = ntile;

    // Phase 1: gelu -> fp16 split into sb[0,32K) hi, [32K,64K) lo
    // rows 256B, 16 chunks, swizzle ch ^ (row&7)
    #pragma unroll
    for (int mi = 0; mi < 4; ++mi) {
        #pragma unroll
        for (int ni = 0; ni < 4; ++ni) {
            int row0 = m0w + mi * 16 + gq;
            int col  = n0w + ni * 8 + tg * 2;
            uint32_t ch = (uint32_t)(col >> 3);
            uint32_t wi = (uint32_t)((col & 7) * 2);
            #pragma unroll
            for (int r2 = 0; r2 < 2; ++r2) {
                int row = row0 + r2 * 8;
                float v0 = gelu_exact(acc[mi][ni][2 * r2 + 0]);
                float v1 = gelu_exact(acc[mi][ni][2 * r2 + 1]);
                uint32_t h = pack_h2(v0, v1);
                uint32_t l = pack_h2(h_res(v0), h_res(v1));
                uint32_t a = sb + row * 256 + ((ch ^ (uint32_t)(row & 7)) << 4) + wi;
                asm volatile("st.shared.u32 [%0], %1;" :: "r"(a), "r"(h) : "memory");
                asm volatile("st.shared.u32 [%0], %1;" :: "r"(a + 32768), "r"(l) : "memory");
            }
        }
    }

    // Phase 2: 128x128x128 3-term fp16 MMA with qkwT[c] (2 k-halves of 64)
    float acc2[4][4][4];
    #pragma unroll
    for (int mi = 0; mi < 4; ++mi)
        #pragma unroll
        for (int ni = 0; ni < 4; ++ni)
            #pragma unroll
            for (int r = 0; r < 4; ++r) acc2[mi][ni][r] = 0.0f;

    const uint32_t wb = sb + 65536;   // Q region: hi 16K, lo 16K
    for (int kb = 0; kb < 2; ++kb) {
        __syncthreads();
        #pragma unroll
        for (int q = 0; q < 4; ++q) {
            int cc = tid + q * 256;
            int j  = cc >> 3, ch = cc & 7;
            uint32_t dst = wb + j * 128 + (uint32_t)((ch ^ (j & 7)) << 4);
            size_t so = ((size_t)(c * KDIM + j)) * KDIM + kb * 64 + ch * 8;
            CPA16(dst, g_Qhi + so);
            CPA16(dst + 16384, g_Qlo + so);
        }
        CPA_COMMIT();
        CPA_WAIT0();
        __syncthreads();

        #pragma unroll
        for (int ksl = 0; ksl < 4; ++ksl) {
            uint32_t bh[4][2], bl[4][2];
            #pragma unroll
            for (int p = 0; p < 2; ++p) {
                int rowB = n0w + p * 16 + rowBoff;
                int cB   = ksl * 2 + cBoff;
                uint32_t aW = wb + rowB * 128
                            + (uint32_t)((cB ^ (rowB & 7)) << 4);
                uint32_t t[4];
                ldsm_x4(aW, t);
                bh[2*p][0] = t[0]; bh[2*p][1] = t[1];
                bh[2*p+1][0] = t[2]; bh[2*p+1][1] = t[3];
                ldsm_x4(aW + 16384, t);
                bl[2*p][0] = t[0]; bl[2*p][1] = t[1];
                bl[2*p+1][0] = t[2]; bl[2*p+1][1] = t[3];
            }
            #pragma unroll
            for (int mi = 0; mi < 4; ++mi) {
                int rowA = m0w + mi * 16 + rowAoff;
                int cA   = kb * 8 + ksl * 2 + cAoff;
                uint32_t aA = sb + rowA * 256
                            + (uint32_t)((cA ^ (rowA & 7)) << 4);
                uint32_t ah[4], al[4];
                ldsm_x4(aA, ah);
                ldsm_x4(aA + 32768, al);
                #pragma unroll
                for (int ni = 0; ni < 4; ++ni) {
                    mma16816(acc2[mi][ni], ah, bh[ni]);
                    mma16816(acc2[mi][ni], ah, bl[ni]);
                    mma16816(acc2[mi][ni], al, bh[ni]);
                }
            }
        }
    }

    // Phase 3: RMS over M=32 (warp's 32 cols = one ii group) + stores
    const int ii = n0w >> 5;
    #pragma unroll
    for (int mi = 0; mi < 4; ++mi) {
        int row0 = m0w + mi * 16 + gq;
        #pragma unroll
        for (int r2 = 0; r2 < 2; ++r2) {
            int r = mbase + row0 + r2 * 8;
            float ss = 0.0f;
            #pragma unroll
            for (int ni = 0; ni < 4; ++ni) {
                ss = fmaf(acc2[mi][ni][2*r2+0], acc2[mi][ni][2*r2+0], ss);
                ss = fmaf(acc2[mi][ni][2*r2+1], acc2[mi][ni][2*r2+1], ss);
            }
            ss += __shfl_xor_sync(0xffffffffu, ss, 1);
            ss += __shfl_xor_sync(0xffffffffu, ss, 2);

            if (ii < 2) {
                float scale = rsqrtf(ss * (1.0f / 32.0f) + 1e-6f);
                #pragma unroll
                for (int ni = 0; ni < 4; ++ni) {
                    int m = (n0w & 31) + ni * 8 + tg * 2;
                    float2 o = make_float2(acc2[mi][ni][2*r2+0] * scale,
                                           acc2[mi][ni][2*r2+1] * scale);
                    *reinterpret_cast<float2*>(
                        &w1n_out[(size_t)r * 256 + c * 64 + ii * 32 + m]) = o;
                }
            } else {
                #pragma unroll
                for (int ni = 0; ni < 4; ++ni) {
                    int m = (n0w & 31) + ni * 8 + tg * 2;
                    float2 o = make_float2(acc2[mi][ni][2*r2+0],
                                           acc2[mi][ni][2*r2+1]);
                    *reinterpret_cast<float2*>(
                        &w2_out[(size_t)r * 256 + c * 64 + (ii - 2) * 32 + m]) = o;
                }
            }
        }
    }
}

// ---------------------------------------------------------------------------
extern "C" void kernel_launch(void* const* d_in, const int* in_sizes, int n_in,
                              void* d_out, int out_size) {
    const float* query = (const float*)d_in[0];
    // d_in[1] = key_vec (unused by reference)
    const float* dw1   = (const float*)d_in[2];
    const float* qkw   = (const float*)d_in[3];
    const float* dd_p  = (const float*)d_in[4];

    float* out = (float*)d_out;
    float* w1n = out;
    float* w2  = out + W2_BASE;
    float* dd  = out + DD_BASE;

    cudaFuncSetAttribute(gemm1_mma, cudaFuncAttributeMaxDynamicSharedMemorySize, GEMM1_SMEM);

    conv_w<<<dim3(NTOT / 32, DDIM / 32), dim3(32, 8)>>>(dw1, dd_p);
    conv_q<<<dim3(4, 4, 4), dim3(32, 8)>>>(qkw);
    gemm1_mma<<<dim3(5, 64), 256, GEMM1_SMEM>>>(query, w1n, w2, dd);
}

// round 7
// speedup vs baseline: 5.8007x; 1.6045x over previous
#include <cuda_runtime.h>
#include <cuda_fp16.h>
#include <cmath>
#include <cstdint>

// ---------------- problem constants ----------------
#define BT    8192
#define DDIM  4096
#define NH    512
#define NDD   128
#define NTOT  640
#define KDIM  128

#define W2_BASE  (BT * 4 * 2 * 32)   // 2,097,152
#define DD_BASE  (2 * W2_BASE)

// ---------------- device scratch ----------------
__device__ __half g_Wh[(size_t)NTOT * DDIM];      // [n][k] fp16
__device__ __half g_Qhi[4 * KDIM * KDIM];         // qkwT split: [c][j][k]
__device__ __half g_Qlo[4 * KDIM * KDIM];

__device__ __forceinline__ float gelu_exact(float x) {
    return 0.5f * x * (1.0f + erff(x * 0.70710678118654752f));
}

#define CPA16(dst, src) \
    asm volatile("cp.async.cg.shared.global [%0], [%1], 16;" :: "r"(dst), "l"(src) : "memory")
#define CPA_COMMIT() asm volatile("cp.async.commit_group;" ::: "memory")
#define CPA_WAIT2()  asm volatile("cp.async.wait_group 2;" ::: "memory")
#define CPA_WAIT0()  asm volatile("cp.async.wait_group 0;" ::: "memory")

__device__ __forceinline__ uint32_t smem_u32(const void* p) {
    uint32_t a;
    asm("{ .reg .u64 t; cvta.to.shared.u64 t, %1; cvt.u32.u64 %0, t; }" : "=r"(a) : "l"(p));
    return a;
}

__device__ __forceinline__ void mma16816(float* d, const uint32_t* a, const uint32_t* b) {
    asm volatile(
        "mma.sync.aligned.m16n8k16.row.col.f32.f16.f16.f32 "
        "{%0,%1,%2,%3}, {%4,%5,%6,%7}, {%8,%9}, {%0,%1,%2,%3};"
        : "+f"(d[0]), "+f"(d[1]), "+f"(d[2]), "+f"(d[3])
        : "r"(a[0]), "r"(a[1]), "r"(a[2]), "r"(a[3]), "r"(b[0]), "r"(b[1]));
}

__device__ __forceinline__ void ldsm_x4(uint32_t addr, uint32_t* r) {
    asm volatile("ldmatrix.sync.aligned.m8n8.x4.shared.b16 {%0,%1,%2,%3}, [%4];"
        : "=r"(r[0]), "=r"(r[1]), "=r"(r[2]), "=r"(r[3]) : "r"(addr));
}

__device__ __forceinline__ uint32_t pack_h2(float a, float b) {
    __half2 h = __floats2half2_rn(a, b);
    return *reinterpret_cast<uint32_t*>(&h);
}
__device__ __forceinline__ float h_res(float x) {
    return x - __half2float(__float2half_rn(x));
}

// ---------------------------------------------------------------------------
// conv_w: transpose [dw1 | dd_p] -> Wh [640][4096] fp16 (K-major)
// ---------------------------------------------------------------------------
__global__ __launch_bounds__(256) void conv_w(const float* __restrict__ dw1,
                                              const float* __restrict__ ddp) {
    __shared__ float t[32][33];
    int n0 = blockIdx.x * 32, k0 = blockIdx.y * 32;
    int tx = threadIdx.x, ty = threadIdx.y;
    const float* src = (n0 < NH) ? dw1 : ddp;
    int ld   = (n0 < NH) ? NH : NDD;
    int ncol = (n0 < NH) ? (n0 + tx) : (n0 - NH + tx);
    #pragma unroll
    for (int j = 0; j < 4; ++j)
        t[ty + 8 * j][tx] = src[(size_t)(k0 + ty + 8 * j) * ld + ncol];
    __syncthreads();
    #pragma unroll
    for (int j = 0; j < 4; ++j) {
        int n = n0 + ty + 8 * j, k = k0 + tx;
        g_Wh[(size_t)n * DDIM + k] = __float2half_rn(t[tx][ty + 8 * j]);
    }
}

// ---------------------------------------------------------------------------
// conv_q: transpose+split qkw [c][k][j] -> Qhi/Qlo [c][j][k] fp16
// ---------------------------------------------------------------------------
__global__ __launch_bounds__(256) void conv_q(const float* __restrict__ qkw) {
    __shared__ float t[32][33];
    int c = blockIdx.x, j0 = blockIdx.y * 32, k0 = blockIdx.z * 32;
    int tx = threadIdx.x, ty = threadIdx.y;
    #pragma unroll
    for (int jj = 0; jj < 4; ++jj)
        t[ty + 8 * jj][tx] = qkw[((c * KDIM) + (k0 + ty + 8 * jj)) * KDIM + j0 + tx];
    __syncthreads();
    #pragma unroll
    for (int jj = 0; jj < 4; ++jj) {
        int j = j0 + ty + 8 * jj, k = k0 + tx;
        float v = t[tx][ty + 8 * jj];
        __half h = __float2half_rn(v);
        g_Qhi[(c * KDIM + j) * KDIM + k] = h;
        g_Qlo[(c * KDIM + j) * KDIM + k] = __float2half_rn(v - __half2float(h));
    }
}

// ---------------------------------------------------------------------------
// gemm1_mma: [8192,4096] x [4096,640], single-term fp16 (ah*wh).
// CTA 128x128, BK=32, A double-buffered fp16 (2x8K), W 4-stage (4x8K),
// 96KB smem (epilogue needs it), 2 CTAs/SM, one __syncthreads per iter.
// ntile<4: fused second-GEMM epilogue (gelu -> fp16 split -> 3-term MMA with
// qkwT -> RMS -> w1n/w2). ntile==4: tanh -> dd.
// ---------------------------------------------------------------------------
#define ABUF_B  8192
#define WST_B   8192
#define W_OFF   16384
#define GEMM1_SMEM 98304

__global__ __launch_bounds__(256, 2) void gemm1_mma(
    const float* __restrict__ X,
    float* __restrict__ w1n_out, float* __restrict__ w2_out,
    float* __restrict__ dd_out) {
    extern __shared__ char smem[];
    uint32_t sb = smem_u32(smem);

    const int tid  = threadIdx.x;
    const int wid  = tid >> 5;
    const int lane = tid & 31;
    const int gq   = lane >> 2;
    const int tg   = lane & 3;

    const int ntile = blockIdx.x;          // 0..4
    const int mbase = blockIdx.y << 7;
    const int m0w   = (wid & 1) * 64;
    const int n0w   = (wid >> 1) * 32;

    const float* Xrow = X + (size_t)mbase * DDIM;
    const __half* Whrow = g_Wh + (size_t)(ntile * 128) * DDIM;

    // A LDG geometry: 4 chunks of 16B f32 per thread (128 rows x 32 k f32)
    int aRow[4], aCh[4];
    uint32_t aSts[4];
    #pragma unroll
    for (int q = 0; q < 4; ++q) {
        int cc = tid + q * 256;
        aRow[q] = cc >> 3; aCh[q] = cc & 7;
        aSts[q] = (uint32_t)(aRow[q] * 64
                + ((((aCh[q] >> 1) ^ ((aRow[q] >> 1) & 3)) << 4) + ((aCh[q] & 1) << 3)));
    }
    // W cp.async geometry: 8KB/stage -> 2 chunks of 16B per thread
    int wRow[2], wCh[2];
    #pragma unroll
    for (int q = 0; q < 2; ++q) { int cc = tid + q * 256; wRow[q] = cc >> 2; wCh[q] = cc & 3; }

    auto w_refill = [&](uint32_t stg, int k0) {
        #pragma unroll
        for (int q = 0; q < 2; ++q) {
            uint32_t dst = stg + wRow[q] * 64
                         + (uint32_t)((wCh[q] ^ ((wRow[q] >> 1) & 3)) << 4);
            CPA16(dst, Whrow + (size_t)wRow[q] * DDIM + k0 + wCh[q] * 8);
        }
    };

    float4 xreg[4];
    auto a_ldg = [&](int k0) {
        #pragma unroll
        for (int q = 0; q < 4; ++q)
            xreg[q] = *reinterpret_cast<const float4*>(
                &Xrow[(size_t)aRow[q] * DDIM + k0 + aCh[q] * 4]);
    };
    auto a_sts = [&](uint32_t abuf) {
        #pragma unroll
        for (int q = 0; q < 4; ++q) {
            float4 v = xreg[q];
            uint32_t h0 = pack_h2(v.x, v.y), h1 = pack_h2(v.z, v.w);
            uint32_t a = abuf + aSts[q];
            asm volatile("st.shared.v2.u32 [%0], {%1,%2};" :: "r"(a), "r"(h0), "r"(h1) : "memory");
        }
    };

    // ldmatrix lane geometry
    const int rowAoff = ((lane >> 3) & 1) * 8 + (lane & 7);
    const int cAoff   = (lane >> 4) & 1;
    const int rowBoff = ((lane >> 4) & 1) * 8 + (lane & 7);
    const int cBoff   = (lane >> 3) & 1;

    // ---- prologue ----
    a_ldg(0);
    a_sts(sb);
    a_ldg(32);
    w_refill(sb + W_OFF, 0);              CPA_COMMIT();
    w_refill(sb + W_OFF + WST_B, 32);     CPA_COMMIT();
    w_refill(sb + W_OFF + 2 * WST_B, 64); CPA_COMMIT();

    float acc[4][4][4];
    #pragma unroll
    for (int mi = 0; mi < 4; ++mi)
        #pragma unroll
        for (int ni = 0; ni < 4; ++ni)
            #pragma unroll
            for (int r = 0; r < 4; ++r) acc[mi][ni][r] = 0.0f;

    const int NKT = DDIM / 32;  // 128

    for (int it = 0; it < NKT; ++it) {
        uint32_t abuf = sb + (uint32_t)(it & 1) * ABUF_B;
        uint32_t wstg = sb + W_OFF + (uint32_t)(it & 3) * WST_B;

        CPA_WAIT2();
        __syncthreads();

        if (it + 1 < NKT) a_sts(sb + (uint32_t)((it + 1) & 1) * ABUF_B);
        if (it + 2 < NKT) a_ldg((it + 2) * 32);

        #pragma unroll
        for (int ks = 0; ks < 2; ++ks) {
            int c0 = ks * 2;
            uint32_t bh[4][2];
            #pragma unroll
            for (int p = 0; p < 2; ++p) {
                int rowB = n0w + p * 16 + rowBoff;
                int cB   = c0 + cBoff;
                uint32_t aW = wstg + rowB * 64
                            + (uint32_t)((cB ^ ((rowB >> 1) & 3)) << 4);
                uint32_t t[4];
                ldsm_x4(aW, t);
                bh[2*p][0] = t[0]; bh[2*p][1] = t[1];
                bh[2*p+1][0] = t[2]; bh[2*p+1][1] = t[3];
            }
            #pragma unroll
            for (int mi = 0; mi < 4; ++mi) {
                int rowA = m0w + mi * 16 + rowAoff;
                int cA   = c0 + cAoff;
                uint32_t aA = abuf + rowA * 64
                            + (uint32_t)((cA ^ ((rowA >> 1) & 3)) << 4);
                uint32_t ah[4];
                ldsm_x4(aA, ah);
                #pragma unroll
                for (int ni = 0; ni < 4; ++ni)
                    mma16816(acc[mi][ni], ah, bh[ni]);
            }
        }

        if (it + 3 < NKT)
            w_refill(sb + W_OFF + (uint32_t)((it + 3) & 3) * WST_B, (it + 3) * 32);
        CPA_COMMIT();
    }

    CPA_WAIT0();
    __syncthreads();

    // ================= epilogue =================
    if (ntile == 4) {
        #pragma unroll
        for (int mi = 0; mi < 4; ++mi) {
            #pragma unroll
            for (int ni = 0; ni < 4; ++ni) {
                int row = mbase + m0w + mi * 16 + gq;
                int col = n0w + ni * 8 + tg * 2;
                float2 o0 = make_float2(tanhf(acc[mi][ni][0]), tanhf(acc[mi][ni][1]));
                float2 o1 = make_float2(tanhf(acc[mi][ni][2]), tanhf(acc[mi][ni][3]));
                *reinterpret_cast<float2*>(&dd_out[(size_t)row * NDD + col])       = o0;
                *reinterpret_cast<float2*>(&dd_out[(size_t)(row + 8) * NDD + col]) = o1;
            }
        }
        return;
    }

    const int c = ntile;

    // Phase 1: gelu -> fp16 split into sb[0,32K) hi, [32K,64K) lo
    // rows 256B, 16 chunks, swizzle ch ^ (row&7)
    #pragma unroll
    for (int mi = 0; mi < 4; ++mi) {
        #pragma unroll
        for (int ni = 0; ni < 4; ++ni) {
            int row0 = m0w + mi * 16 + gq;
            int col  = n0w + ni * 8 + tg * 2;
            uint32_t ch = (uint32_t)(col >> 3);
            uint32_t wi = (uint32_t)((col & 7) * 2);
            #pragma unroll
            for (int r2 = 0; r2 < 2; ++r2) {
                int row = row0 + r2 * 8;
                float v0 = gelu_exact(acc[mi][ni][2 * r2 + 0]);
                float v1 = gelu_exact(acc[mi][ni][2 * r2 + 1]);
                uint32_t h = pack_h2(v0, v1);
                uint32_t l = pack_h2(h_res(v0), h_res(v1));
                uint32_t a = sb + row * 256 + ((ch ^ (uint32_t)(row & 7)) << 4) + wi;
                asm volatile("st.shared.u32 [%0], %1;" :: "r"(a), "r"(h) : "memory");
                asm volatile("st.shared.u32 [%0], %1;" :: "r"(a + 32768), "r"(l) : "memory");
            }
        }
    }

    // Phase 2: 128x128x128 3-term fp16 MMA with qkwT[c] (2 k-halves of 64)
    float acc2[4][4][4];
    #pragma unroll
    for (int mi = 0; mi < 4; ++mi)
        #pragma unroll
        for (int ni = 0; ni < 4; ++ni)
            #pragma unroll
            for (int r = 0; r < 4; ++r) acc2[mi][ni][r] = 0.0f;

    const uint32_t wb = sb + 65536;   // Q region: hi 16K, lo 16K
    for (int kb = 0; kb < 2; ++kb) {
        __syncthreads();
        #pragma unroll
        for (int q = 0; q < 4; ++q) {
            int cc = tid + q * 256;
            int j  = cc >> 3, ch = cc & 7;
            uint32_t dst = wb + j * 128 + (uint32_t)((ch ^ (j & 7)) << 4);
            size_t so = ((size_t)(c * KDIM + j)) * KDIM + kb * 64 + ch * 8;
            CPA16(dst, g_Qhi + so);
            CPA16(dst + 16384, g_Qlo + so);
        }
        CPA_COMMIT();
        CPA_WAIT0();
        __syncthreads();

        #pragma unroll
        for (int ksl = 0; ksl < 4; ++ksl) {
            uint32_t bh[4][2], bl[4][2];
            #pragma unroll
            for (int p = 0; p < 2; ++p) {
                int rowB = n0w + p * 16 + rowBoff;
                int cB   = ksl * 2 + cBoff;
                uint32_t aW = wb + rowB * 128
                            + (uint32_t)((cB ^ (rowB & 7)) << 4);
                uint32_t t[4];
                ldsm_x4(aW, t);
                bh[2*p][0] = t[0]; bh[2*p][1] = t[1];
                bh[2*p+1][0] = t[2]; bh[2*p+1][1] = t[3];
                ldsm_x4(aW + 16384, t);
                bl[2*p][0] = t[0]; bl[2*p][1] = t[1];
                bl[2*p+1][0] = t[2]; bl[2*p+1][1] = t[3];
            }
            #pragma unroll
            for (int mi = 0; mi < 4; ++mi) {
                int rowA = m0w + mi * 16 + rowAoff;
                int cA   = kb * 8 + ksl * 2 + cAoff;
                uint32_t aA = sb + rowA * 256
                            + (uint32_t)((cA ^ (rowA & 7)) << 4);
                uint32_t ah[4], al[4];
                ldsm_x4(aA, ah);
                ldsm_x4(aA + 32768, al);
                #pragma unroll
                for (int ni = 0; ni < 4; ++ni) {
                    mma16816(acc2[mi][ni], ah, bh[ni]);
                    mma16816(acc2[mi][ni], ah, bl[ni]);
                    mma16816(acc2[mi][ni], al, bh[ni]);
                }
            }
        }
    }

    // Phase 3: RMS over M=32 (warp's 32 cols = one ii group) + stores
    const int ii = n0w >> 5;
    #pragma unroll
    for (int mi = 0; mi < 4; ++mi) {
        int row0 = m0w + mi * 16 + gq;
        #pragma unroll
        for (int r2 = 0; r2 < 2; ++r2) {
            int r = mbase + row0 + r2 * 8;
            float ss = 0.0f;
            #pragma unroll
            for (int ni = 0; ni < 4; ++ni) {
                ss = fmaf(acc2[mi][ni][2*r2+0], acc2[mi][ni][2*r2+0], ss);
                ss = fmaf(acc2[mi][ni][2*r2+1], acc2[mi][ni][2*r2+1], ss);
            }
            ss += __shfl_xor_sync(0xffffffffu, ss, 1);
            ss += __shfl_xor_sync(0xffffffffu, ss, 2);

            if (ii < 2) {
                float scale = rsqrtf(ss * (1.0f / 32.0f) + 1e-6f);
                #pragma unroll
                for (int ni = 0; ni < 4; ++ni) {
                    int m = (n0w & 31) + ni * 8 + tg * 2;
                    float2 o = make_float2(acc2[mi][ni][2*r2+0] * scale,
                                           acc2[mi][ni][2*r2+1] * scale);
                    *reinterpret_cast<float2*>(
                        &w1n_out[(size_t)r * 256 + c * 64 + ii * 32 + m]) = o;
                }
            } else {
                #pragma unroll
                for (int ni = 0; ni < 4; ++ni) {
                    int m = (n0w & 31) + ni * 8 + tg * 2;
                    float2 o = make_float2(acc2[mi][ni][2*r2+0],
                                           acc2[mi][ni][2*r2+1]);
                    *reinterpret_cast<float2*>(
                        &w2_out[(size_t)r * 256 + c * 64 + (ii - 2) * 32 + m]) = o;
                }
            }
        }
    }
}

// ---------------------------------------------------------------------------
extern "C" void kernel_launch(void* const* d_in, const int* in_sizes, int n_in,
                              void* d_out, int out_size) {
    const float* query = (const float*)d_in[0];
    // d_in[1] = key_vec (unused by reference)
    const float* dw1   = (const float*)d_in[2];
    const float* qkw   = (const float*)d_in[3];
    const float* dd_p  = (const float*)d_in[4];

    float* out = (float*)d_out;
    float* w1n = out;
    float* w2  = out + W2_BASE;
    float* dd  = out + DD_BASE;

    cudaFuncSetAttribute(gemm1_mma, cudaFuncAttributeMaxDynamicSharedMemorySize, GEMM1_SMEM);

    conv_w<<<dim3(NTOT / 32, DDIM / 32), dim3(32, 8)>>>(dw1, dd_p);
    conv_q<<<dim3(4, 4, 4), dim3(32, 8)>>>(qkw);
    gemm1_mma<<<dim3(5, 64), 256, GEMM1_SMEM>>>(query, w1n, w2, dd);
}

// round 8
// speedup vs baseline: 6.2844x; 1.0834x over previous
#include <cuda_runtime.h>
#include <cuda_fp16.h>
#include <cmath>
#include <cstdint>

// ---------------- problem constants ----------------
#define BT    8192
#define DDIM  4096
#define NH    512
#define NDD   128
#define NTOT  640
#define KDIM  128

#define W2_BASE  (BT * 4 * 2 * 32)   // 2,097,152
#define DD_BASE  (2 * W2_BASE)

// ---------------- device scratch ----------------
__device__ __half g_Wh[(size_t)NTOT * DDIM];      // [n][k] fp16
__device__ __half g_Qh[4 * KDIM * KDIM];          // qkwT fp16: [c][j][k]

__device__ __forceinline__ float gelu_exact(float x) {
    return 0.5f * x * (1.0f + erff(x * 0.70710678118654752f));
}

#define CPA16(dst, src) \
    asm volatile("cp.async.cg.shared.global [%0], [%1], 16;" :: "r"(dst), "l"(src) : "memory")
#define CPA_COMMIT() asm volatile("cp.async.commit_group;" ::: "memory")
#define CPA_WAIT2()  asm volatile("cp.async.wait_group 2;" ::: "memory")
#define CPA_WAIT0()  asm volatile("cp.async.wait_group 0;" ::: "memory")

__device__ __forceinline__ uint32_t smem_u32(const void* p) {
    uint32_t a;
    asm("{ .reg .u64 t; cvta.to.shared.u64 t, %1; cvt.u32.u64 %0, t; }" : "=r"(a) : "l"(p));
    return a;
}

__device__ __forceinline__ void mma16816(float* d, const uint32_t* a, const uint32_t* b) {
    asm volatile(
        "mma.sync.aligned.m16n8k16.row.col.f32.f16.f16.f32 "
        "{%0,%1,%2,%3}, {%4,%5,%6,%7}, {%8,%9}, {%0,%1,%2,%3};"
        : "+f"(d[0]), "+f"(d[1]), "+f"(d[2]), "+f"(d[3])
        : "r"(a[0]), "r"(a[1]), "r"(a[2]), "r"(a[3]), "r"(b[0]), "r"(b[1]));
}

__device__ __forceinline__ void ldsm_x4(uint32_t addr, uint32_t* r) {
    asm volatile("ldmatrix.sync.aligned.m8n8.x4.shared.b16 {%0,%1,%2,%3}, [%4];"
        : "=r"(r[0]), "=r"(r[1]), "=r"(r[2]), "=r"(r[3]) : "r"(addr));
}

__device__ __forceinline__ uint32_t pack_h2(float a, float b) {
    __half2 h = __floats2half2_rn(a, b);
    return *reinterpret_cast<uint32_t*>(&h);
}
__device__ __forceinline__ float h_res(float x) {
    return x - __half2float(__float2half_rn(x));
}

// ---------------------------------------------------------------------------
// conv_w: transpose [dw1 | dd_p] -> Wh [640][4096] fp16 (K-major)
// ---------------------------------------------------------------------------
__global__ __launch_bounds__(256) void conv_w(const float* __restrict__ dw1,
                                              const float* __restrict__ ddp) {
    __shared__ float t[32][33];
    int n0 = blockIdx.x * 32, k0 = blockIdx.y * 32;
    int tx = threadIdx.x, ty = threadIdx.y;
    const float* src = (n0 < NH) ? dw1 : ddp;
    int ld   = (n0 < NH) ? NH : NDD;
    int ncol = (n0 < NH) ? (n0 + tx) : (n0 - NH + tx);
    #pragma unroll
    for (int j = 0; j < 4; ++j)
        t[ty + 8 * j][tx] = src[(size_t)(k0 + ty + 8 * j) * ld + ncol];
    __syncthreads();
    #pragma unroll
    for (int j = 0; j < 4; ++j) {
        int n = n0 + ty + 8 * j, k = k0 + tx;
        g_Wh[(size_t)n * DDIM + k] = __float2half_rn(t[tx][ty + 8 * j]);
    }
}

// ---------------------------------------------------------------------------
// conv_q: transpose qkw [c][k][j] -> Qh [c][j][k] fp16 (single term)
// ---------------------------------------------------------------------------
__global__ __launch_bounds__(256) void conv_q(const float* __restrict__ qkw) {
    __shared__ float t[32][33];
    int c = blockIdx.x, j0 = blockIdx.y * 32, k0 = blockIdx.z * 32;
    int tx = threadIdx.x, ty = threadIdx.y;
    #pragma unroll
    for (int jj = 0; jj < 4; ++jj)
        t[ty + 8 * jj][tx] = qkw[((c * KDIM) + (k0 + ty + 8 * jj)) * KDIM + j0 + tx];
    __syncthreads();
    #pragma unroll
    for (int jj = 0; jj < 4; ++jj) {
        int j = j0 + ty + 8 * jj, k = k0 + tx;
        g_Qh[(c * KDIM + j) * KDIM + k] = __float2half_rn(t[tx][ty + 8 * jj]);
    }
}

// ---------------------------------------------------------------------------
// gemm1_mma: [8192,4096] x [4096,640], single-term fp16 mainloop.
// CTA 64x128, BK=32, 128 threads (warp grid 2Mx2N, warp tile 32x64), occ 4.
// Smem (48K): mainloop A 2x4K [0,8K) + W 4x8K [8K,40K);
// epilogue Ahi [0,16K) + Alo [16K,32K) + Q [32K,48K).
// ntile<4: fused 2nd GEMM (gelu -> fp16 2-term split, Q single-term) + RMS.
// ntile==4: tanh -> dd.
// ---------------------------------------------------------------------------
#define ABUF_B  4096
#define WST_B   8192
#define W_OFF   8192
#define GEMM1_SMEM 49152

__global__ __launch_bounds__(128, 4) void gemm1_mma(
    const float* __restrict__ X,
    float* __restrict__ w1n_out, float* __restrict__ w2_out,
    float* __restrict__ dd_out) {
    extern __shared__ char smem[];
    uint32_t sb = smem_u32(smem);

    const int tid  = threadIdx.x;
    const int wid  = tid >> 5;
    const int lane = tid & 31;
    const int gq   = lane >> 2;
    const int tg   = lane & 3;

    const int ntile = blockIdx.x;          // 0..4
    const int mbase = blockIdx.y << 6;     // 64-row tiles
    const int m0w   = (wid & 1) * 32;
    const int n0w   = (wid >> 1) * 64;

    const float* Xrow = X + (size_t)mbase * DDIM;
    const __half* Whrow = g_Wh + (size_t)(ntile * 128) * DDIM;

    // A LDG geometry: 64 rows x 32 k f32 = 512 16B chunks -> 4 per thread
    int aRow[4], aCh[4];
    uint32_t aSts[4];
    #pragma unroll
    for (int q = 0; q < 4; ++q) {
        int cc = tid + q * 128;
        aRow[q] = cc >> 3; aCh[q] = cc & 7;
        aSts[q] = (uint32_t)(aRow[q] * 64
                + ((((aCh[q] >> 1) ^ ((aRow[q] >> 1) & 3)) << 4) + ((aCh[q] & 1) << 3)));
    }
    // W cp.async geometry: 128 rows x 64B = 512 chunks -> 4 per thread
    int wRow[4], wCh[4];
    #pragma unroll
    for (int q = 0; q < 4; ++q) { int cc = tid + q * 128; wRow[q] = cc >> 2; wCh[q] = cc & 3; }

    auto w_refill = [&](uint32_t stg, int k0) {
        #pragma unroll
        for (int q = 0; q < 4; ++q) {
            uint32_t dst = stg + wRow[q] * 64
                         + (uint32_t)((wCh[q] ^ ((wRow[q] >> 1) & 3)) << 4);
            CPA16(dst, Whrow + (size_t)wRow[q] * DDIM + k0 + wCh[q] * 8);
        }
    };

    float4 xreg[4];
    auto a_ldg = [&](int k0) {
        #pragma unroll
        for (int q = 0; q < 4; ++q)
            xreg[q] = *reinterpret_cast<const float4*>(
                &Xrow[(size_t)aRow[q] * DDIM + k0 + aCh[q] * 4]);
    };
    auto a_sts = [&](uint32_t abuf) {
        #pragma unroll
        for (int q = 0; q < 4; ++q) {
            float4 v = xreg[q];
            uint32_t h0 = pack_h2(v.x, v.y), h1 = pack_h2(v.z, v.w);
            uint32_t a = abuf + aSts[q];
            asm volatile("st.shared.v2.u32 [%0], {%1,%2};" :: "r"(a), "r"(h0), "r"(h1) : "memory");
        }
    };

    // ldmatrix lane geometry
    const int rowAoff = ((lane >> 3) & 1) * 8 + (lane & 7);
    const int cAoff   = (lane >> 4) & 1;
    const int rowBoff = ((lane >> 4) & 1) * 8 + (lane & 7);
    const int cBoff   = (lane >> 3) & 1;

    // ---- prologue ----
    a_ldg(0);
    a_sts(sb);
    a_ldg(32);
    w_refill(sb + W_OFF, 0);              CPA_COMMIT();
    w_refill(sb + W_OFF + WST_B, 32);     CPA_COMMIT();
    w_refill(sb + W_OFF + 2 * WST_B, 64); CPA_COMMIT();

    float acc[2][8][4];
    #pragma unroll
    for (int mi = 0; mi < 2; ++mi)
        #pragma unroll
        for (int ni = 0; ni < 8; ++ni)
            #pragma unroll
            for (int r = 0; r < 4; ++r) acc[mi][ni][r] = 0.0f;

    const int NKT = DDIM / 32;  // 128

    for (int it = 0; it < NKT; ++it) {
        uint32_t abuf = sb + (uint32_t)(it & 1) * ABUF_B;
        uint32_t wstg = sb + W_OFF + (uint32_t)(it & 3) * WST_B;

        CPA_WAIT2();
        __syncthreads();

        if (it + 1 < NKT) a_sts(sb + (uint32_t)((it + 1) & 1) * ABUF_B);
        if (it + 2 < NKT) a_ldg((it + 2) * 32);

        #pragma unroll
        for (int ks = 0; ks < 2; ++ks) {
            int c0 = ks * 2;
            uint32_t bh[8][2];
            #pragma unroll
            for (int p = 0; p < 4; ++p) {
                int rowB = n0w + p * 16 + rowBoff;
                int cB   = c0 + cBoff;
                uint32_t aW = wstg + rowB * 64
                            + (uint32_t)((cB ^ ((rowB >> 1) & 3)) << 4);
                uint32_t t[4];
                ldsm_x4(aW, t);
                bh[2*p][0] = t[0]; bh[2*p][1] = t[1];
                bh[2*p+1][0] = t[2]; bh[2*p+1][1] = t[3];
            }
            #pragma unroll
            for (int mi = 0; mi < 2; ++mi) {
                int rowA = m0w + mi * 16 + rowAoff;
                int cA   = c0 + cAoff;
                uint32_t aA = abuf + rowA * 64
                            + (uint32_t)((cA ^ ((rowA >> 1) & 3)) << 4);
                uint32_t ah[4];
                ldsm_x4(aA, ah);
                #pragma unroll
                for (int ni = 0; ni < 8; ++ni)
                    mma16816(acc[mi][ni], ah, bh[ni]);
            }
        }

        if (it + 3 < NKT)
            w_refill(sb + W_OFF + (uint32_t)((it + 3) & 3) * WST_B, (it + 3) * 32);
        CPA_COMMIT();
    }

    CPA_WAIT0();
    __syncthreads();

    // ================= epilogue =================
    if (ntile == 4) {
        #pragma unroll
        for (int mi = 0; mi < 2; ++mi) {
            #pragma unroll
            for (int ni = 0; ni < 8; ++ni) {
                int row = mbase + m0w + mi * 16 + gq;
                int col = n0w + ni * 8 + tg * 2;
                float2 o0 = make_float2(tanhf(acc[mi][ni][0]), tanhf(acc[mi][ni][1]));
                float2 o1 = make_float2(tanhf(acc[mi][ni][2]), tanhf(acc[mi][ni][3]));
                *reinterpret_cast<float2*>(&dd_out[(size_t)row * NDD + col])       = o0;
                *reinterpret_cast<float2*>(&dd_out[(size_t)(row + 8) * NDD + col]) = o1;
            }
        }
        return;
    }

    const int c = ntile;
    const uint32_t qb = sb + 32768;   // Q region [32K,48K)

    // Issue Q load for kb=0 (overlaps phase-1 gelu/STS below)
    {
        #pragma unroll
        for (int q = 0; q < 8; ++q) {
            int cc = tid + q * 128;
            int j  = cc >> 3, ch = cc & 7;
            uint32_t dst = qb + j * 128 + (uint32_t)((ch ^ (j & 7)) << 4);
            CPA16(dst, g_Qh + ((size_t)(c * KDIM + j)) * KDIM + ch * 8);
        }
        CPA_COMMIT();
    }

    // Phase 1: gelu -> fp16 2-term split into Ahi [0,16K), Alo [16K,32K)
    // rows 256B (128 fp16), 16 chunks, swizzle ch ^ (row&7)
    #pragma unroll
    for (int mi = 0; mi < 2; ++mi) {
        #pragma unroll
        for (int ni = 0; ni < 8; ++ni) {
            int row0 = m0w + mi * 16 + gq;
            int col  = n0w + ni * 8 + tg * 2;
            uint32_t ch = (uint32_t)(col >> 3);
            uint32_t wi = (uint32_t)((col & 7) * 2);
            #pragma unroll
            for (int r2 = 0; r2 < 2; ++r2) {
                int row = row0 + r2 * 8;
                float v0 = gelu_exact(acc[mi][ni][2 * r2 + 0]);
                float v1 = gelu_exact(acc[mi][ni][2 * r2 + 1]);
                uint32_t h = pack_h2(v0, v1);
                uint32_t l = pack_h2(h_res(v0), h_res(v1));
                uint32_t a = sb + row * 256 + ((ch ^ (uint32_t)(row & 7)) << 4) + wi;
                asm volatile("st.shared.u32 [%0], %1;" :: "r"(a), "r"(h) : "memory");
                asm volatile("st.shared.u32 [%0], %1;" :: "r"(a + 16384), "r"(l) : "memory");
            }
        }
    }

    // Phase 2: 64x128x128 2-term MMA (hh*qh + hl*qh), Q single-buffered per kb
    float acc2[2][8][4];
    #pragma unroll
    for (int mi = 0; mi < 2; ++mi)
        #pragma unroll
        for (int ni = 0; ni < 8; ++ni)
            #pragma unroll
            for (int r = 0; r < 4; ++r) acc2[mi][ni][r] = 0.0f;

    for (int kb = 0; kb < 2; ++kb) {
        if (kb == 1) {
            __syncthreads();   // all warps done reading Q buf from kb=0
            #pragma unroll
            for (int q = 0; q < 8; ++q) {
                int cc = tid + q * 128;
                int j  = cc >> 3, ch = cc & 7;
                uint32_t dst = qb + j * 128 + (uint32_t)((ch ^ (j & 7)) << 4);
                CPA16(dst, g_Qh + ((size_t)(c * KDIM + j)) * KDIM + 64 + ch * 8);
            }
            CPA_COMMIT();
        }
        CPA_WAIT0();
        __syncthreads();

        #pragma unroll
        for (int ksl = 0; ksl < 4; ++ksl) {
            uint32_t qh[8][2];
            #pragma unroll
            for (int p = 0; p < 4; ++p) {
                int rowB = n0w + p * 16 + rowBoff;
                int cB   = ksl * 2 + cBoff;
                uint32_t aW = qb + rowB * 128
                            + (uint32_t)((cB ^ (rowB & 7)) << 4);
                uint32_t t[4];
                ldsm_x4(aW, t);
                qh[2*p][0] = t[0]; qh[2*p][1] = t[1];
                qh[2*p+1][0] = t[2]; qh[2*p+1][1] = t[3];
            }
            #pragma unroll
            for (int mi = 0; mi < 2; ++mi) {
                int rowA = m0w + mi * 16 + rowAoff;
                int cA   = kb * 8 + ksl * 2 + cAoff;
                uint32_t aA = sb + rowA * 256
                            + (uint32_t)((cA ^ (rowA & 7)) << 4);
                uint32_t ah[4], al[4];
                ldsm_x4(aA, ah);
                ldsm_x4(aA + 16384, al);
                #pragma unroll
                for (int ni = 0; ni < 8; ++ni) {
                    mma16816(acc2[mi][ni], ah, qh[ni]);
                    mma16816(acc2[mi][ni], al, qh[ni]);
                }
            }
        }
    }

    // Phase 3: RMS over 32-col groups + stores.
    // Warp covers cols n0w..n0w+63 = two ii groups (iiA = n0w>>5, iiB = iiA+1).
    const int iiA = n0w >> 5;     // 0 (w1n pair) or 2 (w2 pair)
    #pragma unroll
    for (int mi = 0; mi < 2; ++mi) {
        #pragma unroll
        for (int r2 = 0; r2 < 2; ++r2) {
            int r = mbase + m0w + mi * 16 + gq + r2 * 8;
            float ssA = 0.0f, ssB = 0.0f;
            #pragma unroll
            for (int ni = 0; ni < 4; ++ni) {
                ssA = fmaf(acc2[mi][ni][2*r2+0], acc2[mi][ni][2*r2+0], ssA);
                ssA = fmaf(acc2[mi][ni][2*r2+1], acc2[mi][ni][2*r2+1], ssA);
                ssB = fmaf(acc2[mi][ni+4][2*r2+0], acc2[mi][ni+4][2*r2+0], ssB);
                ssB = fmaf(acc2[mi][ni+4][2*r2+1], acc2[mi][ni+4][2*r2+1], ssB);
            }
            ssA += __shfl_xor_sync(0xffffffffu, ssA, 1);
            ssA += __shfl_xor_sync(0xffffffffu, ssA, 2);
            ssB += __shfl_xor_sync(0xffffffffu, ssB, 1);
            ssB += __shfl_xor_sync(0xffffffffu, ssB, 2);

            if (iiA == 0) {
                float scA = rsqrtf(ssA * (1.0f / 32.0f) + 1e-6f);
                float scB = rsqrtf(ssB * (1.0f / 32.0f) + 1e-6f);
                #pragma unroll
                for (int ni = 0; ni < 4; ++ni) {
                    int m = ni * 8 + tg * 2;
                    float2 oA = make_float2(acc2[mi][ni][2*r2+0] * scA,
                                            acc2[mi][ni][2*r2+1] * scA);
                    float2 oB = make_float2(acc2[mi][ni+4][2*r2+0] * scB,
                                            acc2[mi][ni+4][2*r2+1] * scB);
                    *reinterpret_cast<float2*>(
                        &w1n_out[(size_t)r * 256 + c * 64 + m]) = oA;
                    *reinterpret_cast<float2*>(
                        &w1n_out[(size_t)r * 256 + c * 64 + 32 + m]) = oB;
                }
            } else {
                #pragma unroll
                for (int ni = 0; ni < 4; ++ni) {
                    int m = ni * 8 + tg * 2;
                    float2 oA = make_float2(acc2[mi][ni][2*r2+0],
                                            acc2[mi][ni][2*r2+1]);
                    float2 oB = make_float2(acc2[mi][ni+4][2*r2+0],
                                            acc2[mi][ni+4][2*r2+1]);
                    *reinterpret_cast<float2*>(
                        &w2_out[(size_t)r * 256 + c * 64 + m]) = oA;
                    *reinterpret_cast<float2*>(
                        &w2_out[(size_t)r * 256 + c * 64 + 32 + m]) = oB;
                }
            }
        }
    }
}

// ---------------------------------------------------------------------------
extern "C" void kernel_launch(void* const* d_in, const int* in_sizes, int n_in,
                              void* d_out, int out_size) {
    const float* query = (const float*)d_in[0];
    // d_in[1] = key_vec (unused by reference)
    const float* dw1   = (const float*)d_in[2];
    const float* qkw   = (const float*)d_in[3];
    const float* dd_p  = (const float*)d_in[4];

    float* out = (float*)d_out;
    float* w1n = out;
    float* w2  = out + W2_BASE;
    float* dd  = out + DD_BASE;

    cudaFuncSetAttribute(gemm1_mma, cudaFuncAttributeMaxDynamicSharedMemorySize, GEMM1_SMEM);

    conv_w<<<dim3(NTOT / 32, DDIM / 32), dim3(32, 8)>>>(dw1, dd_p);
    conv_q<<<dim3(4, 4, 4), dim3(32, 8)>>>(qkw);
    gemm1_mma<<<dim3(5, 128), 128, GEMM1_SMEM>>>(query, w1n, w2, dd);
}